// round 6
// baseline (speedup 1.0000x reference)
#include <cuda_runtime.h>
#include <cstdint>

#define NB   2
#define NC   256
#define NSP  4096
#define NGRP 32
#define CPG  8

// ---------------- scratch (no allocation allowed) ----------------
__device__ float g_ht  [(size_t)NB * NC * NSP];   // hT  [b][n][c]
__device__ float g_qt  [(size_t)NB * NC * NSP];   // qT  [b][n][o]  (pre-scaled by 1/16)
__device__ float g_kt  [(size_t)NB * NC * NSP];   // kT  [b][n][o]
__device__ float g_v   [(size_t)NB * NC * NSP];   // v   [b][o][m]
__device__ float g_ot  [(size_t)NB * NC * NSP];   // outT[b][n][o]
__device__ float g_attn[(size_t)NB * NSP * NSP];  // 128 MiB
__device__ float g_stat[NB * NGRP * 2];

// ---------------- helpers ----------------
__device__ __forceinline__ uint32_t smem_u32(const void* p) {
    uint32_t r;
    asm("{ .reg .u64 t; cvta.to.shared.u64 t, %1; cvt.u32.u64 %0, t; }"
        : "=r"(r) : "l"(p));
    return r;
}

__device__ __forceinline__ float tf32r(float x) {
    uint32_t y;
    asm("cvt.rna.tf32.f32 %0, %1;" : "=r"(y) : "f"(x));
    return __uint_as_float(y);
}

__device__ __forceinline__ void mma8(float* c, const uint32_t* a, const uint32_t* b) {
    asm volatile(
        "mma.sync.aligned.m16n8k8.row.col.f32.tf32.tf32.f32 "
        "{%0,%1,%2,%3}, {%4,%5,%6,%7}, {%8,%9}, {%0,%1,%2,%3};\n"
        : "+f"(c[0]), "+f"(c[1]), "+f"(c[2]), "+f"(c[3])
        : "r"(a[0]), "r"(a[1]), "r"(a[2]), "r"(a[3]),
          "r"(b[0]), "r"(b[1]));
}

__device__ __forceinline__ void ldsm4(uint32_t* r, uint32_t addr) {
    asm volatile(
        "ldmatrix.sync.aligned.m8n8.x4.shared.b16 {%0,%1,%2,%3}, [%4];"
        : "=r"(r[0]), "=r"(r[1]), "=r"(r[2]), "=r"(r[3]) : "r"(addr));
}

// ---------------- GroupNorm stats ----------------
__global__ void gn_stats(const float* __restrict__ x, float* __restrict__ stat)
{
    const int b = blockIdx.x >> 5;
    const int g = blockIdx.x & 31;
    const float* xp = x + ((long)b * NC + (long)g * CPG) * NSP;
    const int tid = threadIdx.x;
    const int TOT = CPG * NSP;

    float s = 0.f, ss = 0.f;
    for (int i = tid * 4; i < TOT; i += 1024) {
        float4 v = *reinterpret_cast<const float4*>(xp + i);
        s  += v.x + v.y + v.z + v.w;
        ss += v.x * v.x + v.y * v.y + v.z * v.z + v.w * v.w;
    }
    __shared__ float rs[256], rss[256];
    rs[tid] = s; rss[tid] = ss;
    __syncthreads();
    for (int off = 128; off > 0; off >>= 1) {
        if (tid < off) { rs[tid] += rs[tid + off]; rss[tid] += rss[tid + off]; }
        __syncthreads();
    }
    if (tid == 0) {
        float mean = rs[0] / (float)TOT;
        float var  = rss[0] / (float)TOT - mean * mean;
        stat[blockIdx.x * 2 + 0] = mean;
        stat[blockIdx.x * 2 + 1] = rsqrtf(var + 1e-5f);
    }
}

// ---------------- GroupNorm apply + transpose: x[b][c][n] -> ht[b][n][c] ----
__global__ void gn_apply(const float* __restrict__ x,
                         const float* __restrict__ w,
                         const float* __restrict__ bb,
                         const float* __restrict__ stat,
                         float* __restrict__ ht)
{
    __shared__ float t[32][33];
    const int b  = blockIdx.z;
    const int c0 = blockIdx.x * 32;
    const int n0 = blockIdx.y * 32;
    const int tx = threadIdx.x, ty = threadIdx.y;
    const float* xb = x  + (long)b * NC * NSP;
    float*       hb = ht + (long)b * NSP * NC;

#pragma unroll
    for (int j = 0; j < 4; j++) {
        const int c = c0 + ty + j * 8;
        const int g = c >> 3;
        const float mean = stat[(b * NGRP + g) * 2 + 0];
        const float inv  = stat[(b * NGRP + g) * 2 + 1];
        const float wc = w[c] * inv;
        const float bc = bb[c] - mean * wc;
        t[ty + j * 8][tx] = xb[(long)c * NSP + n0 + tx] * wc + bc;
    }
    __syncthreads();
#pragma unroll
    for (int j = 0; j < 4; j++) {
        const int n = n0 + ty + j * 8;
        hb[(long)n * NC + c0 + tx] = t[tx][ty + j * 8];
    }
}

// ---------------- row softmax over 4096 ----------------
__global__ void softmax_kernel(float* __restrict__ attn)
{
    float* p = attn + (long)blockIdx.x * NSP;
    const int tid = threadIdx.x;

    float4 v[4];
    float m = -1e30f;
#pragma unroll
    for (int j = 0; j < 4; j++) {
        v[j] = *reinterpret_cast<const float4*>(p + j * 1024 + tid * 4);
        m = fmaxf(m, fmaxf(fmaxf(v[j].x, v[j].y), fmaxf(v[j].z, v[j].w)));
    }
    __shared__ float red[256];
    red[tid] = m; __syncthreads();
    for (int off = 128; off > 0; off >>= 1) {
        if (tid < off) red[tid] = fmaxf(red[tid], red[tid + off]);
        __syncthreads();
    }
    m = red[0]; __syncthreads();

    float s = 0.f;
#pragma unroll
    for (int j = 0; j < 4; j++) {
        v[j].x = __expf(v[j].x - m); v[j].y = __expf(v[j].y - m);
        v[j].z = __expf(v[j].z - m); v[j].w = __expf(v[j].w - m);
        s += v[j].x + v[j].y + v[j].z + v[j].w;
    }
    red[tid] = s; __syncthreads();
    for (int off = 128; off > 0; off >>= 1) {
        if (tid < off) red[tid] += red[tid + off];
        __syncthreads();
    }
    const float invs = 1.f / red[0];
#pragma unroll
    for (int j = 0; j < 4; j++) {
        v[j].x *= invs; v[j].y *= invs; v[j].z *= invs; v[j].w *= invs;
        *reinterpret_cast<float4*>(p + j * 1024 + tid * 4) = v[j];
    }
}

// ---------------------------------------------------------------------------
// tf32 GEMM via mma.sync.m16n8k8 + ldmatrix fragment loads.
//   C[m,n] = (sum_k A[m,k]*B[n,k] + bias) * alpha (+ resid)
//   A: M x K row-major (lda);  B: N x K k-contiguous (ldb);  C row-major (ldc).
// CTA 128x128x(BK=32), 256 thr = 8 warps (2m x 4n), warp tile 64x32.
// smem stride 36 floats (144B rows): ldmatrix row addresses are conflict-free
// (8 rows -> 8 distinct 16B chunks mod 128B).
// Requires M,N % 128 == 0, K % 32 == 0.
// ---------------------------------------------------------------------------
#define TSZ (128 * 36)

template<int BIASCOL, int HASRES>
__global__ __launch_bounds__(256)
void mma_gemm(const float* __restrict__ A, long sA, int lda,
              const float* __restrict__ B, long sB, int ldb,
              float* __restrict__ C, long sC, int ldc,
              int K, float alpha,
              const float* __restrict__ bias,
              const float* __restrict__ resid, long sR)
{
    extern __shared__ float sm[];
    const uint32_t sb = smem_u32(sm);
    const int tid = threadIdx.x;
    const int wid = tid >> 5, lane = tid & 31;
    const int wm = wid >> 2, wn = wid & 3;
    const int g = lane >> 2, t = lane & 3;
    const int bz = blockIdx.z;
    const long bm = (long)blockIdx.y * 128;
    const long bn = (long)blockIdx.x * 128;

    // ldmatrix lane-address decomposition (lane -> matrix j = lane>>3, row = lane&7)
    const int jlo = (lane >> 3) & 1;   // A: row-group select, B: k-half select
    const int jhi = lane >> 4;         // A: k-half select,   B: row-group select
    const int r8  = lane & 7;

    const int rr = tid >> 3, ii = tid & 7;
    const float* gA = A + (long)bz * sA + (bm + rr) * lda + ii * 4;
    const float* gB = B + (long)bz * sB + (bn + rr) * ldb + ii * 4;

    float c[4][4][4];
#pragma unroll
    for (int mi = 0; mi < 4; mi++)
#pragma unroll
        for (int ni = 0; ni < 4; ni++)
#pragma unroll
            for (int j = 0; j < 4; j++) c[mi][ni][j] = 0.f;

    float4 ra[4], rb[4];

#define LDG_TILES(k0) do { \
    _Pragma("unroll") for (int r = 0; r < 4; r++) \
        ra[r] = *reinterpret_cast<const float4*>(gA + (long)(k0) + 32L * r * lda); \
    _Pragma("unroll") for (int r = 0; r < 4; r++) \
        rb[r] = *reinterpret_cast<const float4*>(gB + (long)(k0) + 32L * r * ldb); \
} while (0)

#define STS_TILES(buf) do { \
    float* As_ = sm + (buf) * TSZ + rr * 36 + ii * 4; \
    float* Bs_ = sm + 2 * TSZ + (buf) * TSZ + rr * 36 + ii * 4; \
    _Pragma("unroll") for (int r = 0; r < 4; r++) { \
        float4 v4 = ra[r]; \
        v4.x = tf32r(v4.x); v4.y = tf32r(v4.y); v4.z = tf32r(v4.z); v4.w = tf32r(v4.w); \
        *reinterpret_cast<float4*>(As_ + r * 32 * 36) = v4; } \
    _Pragma("unroll") for (int r = 0; r < 4; r++) { \
        float4 v4 = rb[r]; \
        v4.x = tf32r(v4.x); v4.y = tf32r(v4.y); v4.z = tf32r(v4.z); v4.w = tf32r(v4.w); \
        *reinterpret_cast<float4*>(Bs_ + r * 32 * 36) = v4; } \
} while (0)

    const int nIter = K >> 5;
    LDG_TILES(0);
    STS_TILES(0);
    __syncthreads();

    for (int it = 0; it < nIter; ++it) {
        const int buf = it & 1;
        if (it + 1 < nIter) LDG_TILES((it + 1) * 32);

        // per-buffer ldmatrix base addresses (bytes)
        const uint32_t aAddr = sb + 4u * ((uint32_t)buf * TSZ
                             + (uint32_t)(wm * 64 + jlo * 8 + r8) * 36 + jhi * 4);
        const uint32_t bAddr = sb + 4u * (2u * TSZ + (uint32_t)buf * TSZ
                             + (uint32_t)(wn * 32 + jhi * 8 + r8) * 36 + jlo * 4);

#pragma unroll
        for (int kk = 0; kk < 32; kk += 8) {
            uint32_t a[4][4], b[8];
#pragma unroll
            for (int mi = 0; mi < 4; mi++)
                ldsm4(a[mi], aAddr + 4u * (mi * 16 * 36) + 4u * kk);
#pragma unroll
            for (int nip = 0; nip < 2; nip++)
                ldsm4(&b[nip * 4], bAddr + 4u * (nip * 16 * 36) + 4u * kk);
#pragma unroll
            for (int mi = 0; mi < 4; mi++)
#pragma unroll
                for (int ni = 0; ni < 4; ni++)
                    mma8(c[mi][ni], a[mi], &b[ni * 2]);
        }

        if (it + 1 < nIter) STS_TILES(buf ^ 1);
        __syncthreads();
    }

    // ---------------- register-resident epilogue ----------------
    float* Cz = C + (long)bz * sC;
    const float* Rz = HASRES ? (resid + (long)bz * sR) : nullptr;

#pragma unroll
    for (int mi = 0; mi < 4; mi++) {
        const long row0 = bm + wm * 64 + mi * 16 + g;
        const long row1 = row0 + 8;
        float br0 = 0.f, br1 = 0.f;
        if (!BIASCOL && bias) { br0 = bias[row0]; br1 = bias[row1]; }
#pragma unroll
        for (int ni = 0; ni < 4; ni++) {
            const long col = bn + wn * 32 + ni * 8 + 2 * t;
            float2 v0 = make_float2(c[mi][ni][0], c[mi][ni][1]);
            float2 v1 = make_float2(c[mi][ni][2], c[mi][ni][3]);
            if (BIASCOL) {
                const float bc0 = bias[col], bc1 = bias[col + 1];
                v0.x += bc0; v0.y += bc1; v1.x += bc0; v1.y += bc1;
            } else if (bias) {
                v0.x += br0; v0.y += br0; v1.x += br1; v1.y += br1;
            }
            v0.x *= alpha; v0.y *= alpha; v1.x *= alpha; v1.y *= alpha;
            if (HASRES) {
                float2 r0 = *reinterpret_cast<const float2*>(Rz + row0 * ldc + col);
                float2 r1 = *reinterpret_cast<const float2*>(Rz + row1 * ldc + col);
                v0.x += r0.x; v0.y += r0.y; v1.x += r1.x; v1.y += r1.y;
            }
            *reinterpret_cast<float2*>(Cz + row0 * ldc + col) = v0;
            *reinterpret_cast<float2*>(Cz + row1 * ldc + col) = v1;
        }
    }
#undef LDG_TILES
#undef STS_TILES
}

// ---------------------------------------------------------------------------
extern "C" void kernel_launch(void* const* d_in, const int* in_sizes, int n_in,
                              void* d_out, int out_size)
{
    const float* x   = (const float*)d_in[0];
    const float* gnw = (const float*)d_in[1];
    const float* gnb = (const float*)d_in[2];
    const float* wq  = (const float*)d_in[3];
    const float* bq  = (const float*)d_in[4];
    const float* wk  = (const float*)d_in[5];
    const float* bk  = (const float*)d_in[6];
    const float* wv  = (const float*)d_in[7];
    const float* bv  = (const float*)d_in[8];
    const float* wp  = (const float*)d_in[9];
    const float* bp  = (const float*)d_in[10];
    float* out = (float*)d_out;

    float *ht, *qt, *kt, *v, *ot, *attn, *stat;
    cudaGetSymbolAddress((void**)&ht,   g_ht);
    cudaGetSymbolAddress((void**)&qt,   g_qt);
    cudaGetSymbolAddress((void**)&kt,   g_kt);
    cudaGetSymbolAddress((void**)&v,    g_v);
    cudaGetSymbolAddress((void**)&ot,   g_ot);
    cudaGetSymbolAddress((void**)&attn, g_attn);
    cudaGetSymbolAddress((void**)&stat, g_stat);

    const long sCN = (long)NC * NSP;
    const long sNN = (long)NSP * NSP;
    const int SMEM = 4 * TSZ * 4;   // 73728 bytes

    cudaFuncSetAttribute(mma_gemm<1, 0>, cudaFuncAttributeMaxDynamicSharedMemorySize, SMEM);
    cudaFuncSetAttribute(mma_gemm<0, 0>, cudaFuncAttributeMaxDynamicSharedMemorySize, SMEM);
    cudaFuncSetAttribute(mma_gemm<0, 1>, cudaFuncAttributeMaxDynamicSharedMemorySize, SMEM);

    // 1) GroupNorm -> ht[b][n][c]
    gn_stats<<<NB * NGRP, 256>>>(x, stat);
    gn_apply<<<dim3(NC / 32, NSP / 32, NB), dim3(32, 8)>>>(x, gnw, gnb, stat, ht);

    // 2) q: qt[n][o] = (ht[n][:] . wq[o][:] + bq[o]) / 16   (scale folded in)
    dim3 gQ(NC / 128, NSP / 128, NB);       // 2 x 32 x 2
    mma_gemm<1, 0><<<gQ, 256, SMEM>>>(ht, sCN, NC, wq, 0, NC, qt, sCN, NC,
                                      NC, 0.0625f, bq, nullptr, 0);
    //    k: kt[n][o]
    mma_gemm<1, 0><<<gQ, 256, SMEM>>>(ht, sCN, NC, wk, 0, NC, kt, sCN, NC,
                                      NC, 1.f, bk, nullptr, 0);
    //    v: v[o][m] = wv[o][:] . ht[m][:] + bv[o]
    dim3 gV(NSP / 128, NC / 128, NB);       // 32 x 2 x 2
    mma_gemm<0, 0><<<gV, 256, SMEM>>>(wv, 0, NC, ht, sCN, NC, v, sCN, NSP,
                                      NC, 1.f, bv, nullptr, 0);

    // 3) logits: attn[n][m] = qt[n][:] . kt[m][:]
    dim3 gS(NSP / 128, NSP / 128, NB);      // 32 x 32 x 2
    mma_gemm<0, 0><<<gS, 256, SMEM>>>(qt, sCN, NC, kt, sCN, NC, attn, sNN, NSP,
                                      NC, 1.f, nullptr, nullptr, 0);

    // 4) softmax rows
    softmax_kernel<<<NB * NSP, 256>>>(attn);

    // 5) ot[n][o] = attn[n][:] . v[o][:]
    dim3 gO(NC / 128, NSP / 128, NB);       // 2 x 32 x 2
    mma_gemm<0, 0><<<gO, 256, SMEM>>>(attn, sNN, NSP, v, sCN, NSP, ot, sCN, NC,
                                      NSP, 1.f, nullptr, nullptr, 0);

    // 6) y[o][n] = wp[o][:] . ot[n][:] + bp[o] + x
    mma_gemm<0, 1><<<gV, 256, SMEM>>>(wp, 0, NC, ot, sCN, NC, out, sCN, NSP,
                                      NC, 1.f, bp, x, sCN);
}

// round 8
// speedup vs baseline: 1.1627x; 1.1627x over previous
#include <cuda_runtime.h>
#include <cstdint>

#define NB   2
#define NC   256
#define NSP  4096
#define NGRP 32
#define CPG  8
#define NTIL 32          // 4096/128 column tiles per attn row

// ---------------- scratch (no allocation allowed) ----------------
__device__ float g_ht  [(size_t)NB * NC * NSP];   // hT  [b][n][c]
__device__ float g_qt  [(size_t)NB * NC * NSP];   // qT  [b][n][o]  (pre-scaled by 1/16)
__device__ float g_kt  [(size_t)NB * NC * NSP];   // kT  [b][n][o]
__device__ float g_v   [(size_t)NB * NC * NSP];   // v   [b][o][m]
__device__ float g_ot  [(size_t)NB * NC * NSP];   // outT[b][n][o]
__device__ float g_attn[(size_t)NB * NSP * NSP];  // exp(l - m_tile), 128 MiB
__device__ float g_stat[NB * NGRP * 2];
__device__ float g_pm  [(size_t)NB * NSP * NTIL]; // per (row, tile) max
__device__ float g_ps  [(size_t)NB * NSP * NTIL]; // per (row, tile) sumexp
__device__ float g_sc  [(size_t)NB * NSP * NTIL]; // per (row, tile) final scale

// ---------------- helpers ----------------
__device__ __forceinline__ void mma8(float* c, const uint32_t* a, const uint32_t* b) {
    asm volatile(
        "mma.sync.aligned.m16n8k8.row.col.f32.tf32.tf32.f32 "
        "{%0,%1,%2,%3}, {%4,%5,%6,%7}, {%8,%9}, {%0,%1,%2,%3};\n"
        : "+f"(c[0]), "+f"(c[1]), "+f"(c[2]), "+f"(c[3])
        : "r"(a[0]), "r"(a[1]), "r"(a[2]), "r"(a[3]),
          "r"(b[0]), "r"(b[1]));
}

// ---------------- GroupNorm stats ----------------
__global__ void gn_stats(const float* __restrict__ x, float* __restrict__ stat)
{
    const int b = blockIdx.x >> 5;
    const int g = blockIdx.x & 31;
    const float* xp = x + ((long)b * NC + (long)g * CPG) * NSP;
    const int tid = threadIdx.x;
    const int TOT = CPG * NSP;

    float s = 0.f, ss = 0.f;
    for (int i = tid * 4; i < TOT; i += 1024) {
        float4 v = *reinterpret_cast<const float4*>(xp + i);
        s  += v.x + v.y + v.z + v.w;
        ss += v.x * v.x + v.y * v.y + v.z * v.z + v.w * v.w;
    }
    __shared__ float rs[256], rss[256];
    rs[tid] = s; rss[tid] = ss;
    __syncthreads();
    for (int off = 128; off > 0; off >>= 1) {
        if (tid < off) { rs[tid] += rs[tid + off]; rss[tid] += rss[tid + off]; }
        __syncthreads();
    }
    if (tid == 0) {
        float mean = rs[0] / (float)TOT;
        float var  = rss[0] / (float)TOT - mean * mean;
        stat[blockIdx.x * 2 + 0] = mean;
        stat[blockIdx.x * 2 + 1] = rsqrtf(var + 1e-5f);
    }
}

// ---------------- GroupNorm apply + transpose ----------------
__global__ void gn_apply(const float* __restrict__ x,
                         const float* __restrict__ w,
                         const float* __restrict__ bb,
                         const float* __restrict__ stat,
                         float* __restrict__ ht)
{
    __shared__ float t[32][33];
    const int b  = blockIdx.z;
    const int c0 = blockIdx.x * 32;
    const int n0 = blockIdx.y * 32;
    const int tx = threadIdx.x, ty = threadIdx.y;
    const float* xb = x  + (long)b * NC * NSP;
    float*       hb = ht + (long)b * NSP * NC;

#pragma unroll
    for (int j = 0; j < 4; j++) {
        const int c = c0 + ty + j * 8;
        const int g = c >> 3;
        const float mean = stat[(b * NGRP + g) * 2 + 0];
        const float inv  = stat[(b * NGRP + g) * 2 + 1];
        const float wc = w[c] * inv;
        const float bc = bb[c] - mean * wc;
        t[ty + j * 8][tx] = xb[(long)c * NSP + n0 + tx] * wc + bc;
    }
    __syncthreads();
#pragma unroll
    for (int j = 0; j < 4; j++) {
        const int n = n0 + ty + j * 8;
        hb[(long)n * NC + c0 + tx] = t[tx][ty + j * 8];
    }
}

// =============== common GEMM mainloop pieces (macros) ===============
#define TSZ (128 * 36)

#define GEMM_PREAMBLE \
    extern __shared__ float sm[]; \
    const int tid = threadIdx.x; \
    const int wid = tid >> 5, lane = tid & 31; \
    const int wm = wid >> 2, wn = wid & 3; \
    const int g = lane >> 2, t = lane & 3; \
    const int bz = blockIdx.z; \
    const long bm = (long)blockIdx.y * 128; \
    const long bn = (long)blockIdx.x * 128; \
    const int rr = tid >> 3, ii = tid & 7; \
    float c[4][4][4]; \
    _Pragma("unroll") for (int mi = 0; mi < 4; mi++) \
    _Pragma("unroll") for (int ni = 0; ni < 4; ni++) \
    _Pragma("unroll") for (int j = 0; j < 4; j++) c[mi][ni][j] = 0.f; \
    float4 ra[4], rb[4];

#define LDG_TILES(k0) do { \
    _Pragma("unroll") for (int r = 0; r < 4; r++) \
        ra[r] = *reinterpret_cast<const float4*>(gA + (long)(k0) + 32L * r * lda); \
    _Pragma("unroll") for (int r = 0; r < 4; r++) \
        rb[r] = *reinterpret_cast<const float4*>(gB + (long)(k0) + 32L * r * ldb); \
} while (0)

#define STS_PLAIN(buf) do { \
    float* As_ = sm + (buf) * TSZ + rr * 36 + ii * 4; \
    float* Bs_ = sm + 2 * TSZ + (buf) * TSZ + rr * 36 + ii * 4; \
    _Pragma("unroll") for (int r = 0; r < 4; r++) \
        *reinterpret_cast<float4*>(As_ + r * 32 * 36) = ra[r]; \
    _Pragma("unroll") for (int r = 0; r < 4; r++) \
        *reinterpret_cast<float4*>(Bs_ + r * 32 * 36) = rb[r]; \
} while (0)

// A scaled per row/tile (PV), B plain
#define STS_SCALED(buf, k0) do { \
    float* As_ = sm + (buf) * TSZ + rr * 36 + ii * 4; \
    float* Bs_ = sm + 2 * TSZ + (buf) * TSZ + rr * 36 + ii * 4; \
    const int tm_ = (k0) >> 7; \
    _Pragma("unroll") for (int r = 0; r < 4; r++) { \
        const float f_ = scb[(rr + 32 * r) * NTIL + tm_]; \
        float4 v4 = ra[r]; \
        v4.x *= f_; v4.y *= f_; v4.z *= f_; v4.w *= f_; \
        *reinterpret_cast<float4*>(As_ + r * 32 * 36) = v4; } \
    _Pragma("unroll") for (int r = 0; r < 4; r++) \
        *reinterpret_cast<float4*>(Bs_ + r * 32 * 36) = rb[r]; \
} while (0)

#define MMA_BODY(buf) do { \
    const float* As = sm + (buf) * TSZ + (wm * 64 + g) * 36; \
    const float* Bs = sm + 2 * TSZ + (buf) * TSZ + (wn * 32 + g) * 36; \
    _Pragma("unroll") for (int kk = 0; kk < 32; kk += 8) { \
        uint32_t a[4][4], b[4][2]; \
        _Pragma("unroll") for (int mi = 0; mi < 4; mi++) { \
            const float* ap = As + mi * 16 * 36 + kk + t; \
            a[mi][0] = __float_as_uint(ap[0]); \
            a[mi][1] = __float_as_uint(ap[8 * 36]); \
            a[mi][2] = __float_as_uint(ap[4]); \
            a[mi][3] = __float_as_uint(ap[8 * 36 + 4]); } \
        _Pragma("unroll") for (int ni = 0; ni < 4; ni++) { \
            const float* bp = Bs + ni * 8 * 36 + kk + t; \
            b[ni][0] = __float_as_uint(bp[0]); \
            b[ni][1] = __float_as_uint(bp[4]); } \
        _Pragma("unroll") for (int mi = 0; mi < 4; mi++) \
        _Pragma("unroll") for (int ni = 0; ni < 4; ni++) \
            mma8(c[mi][ni], a[mi], b[ni]); \
    } \
} while (0)

// ---------------------------------------------------------------------------
// generic projection GEMM (q,k,v,out-proj)
// ---------------------------------------------------------------------------
template<int BIASCOL, int HASRES>
__global__ __launch_bounds__(256, 2)
void mma_gemm(const float* __restrict__ A, long sA, int lda,
              const float* __restrict__ B, long sB, int ldb,
              float* __restrict__ C, long sC, int ldc,
              int K, float alpha,
              const float* __restrict__ bias,
              const float* __restrict__ resid, long sR)
{
    GEMM_PREAMBLE
    const float* gA = A + (long)bz * sA + (bm + rr) * lda + ii * 4;
    const float* gB = B + (long)bz * sB + (bn + rr) * ldb + ii * 4;

    const int nIter = K >> 5;
    LDG_TILES(0);
    STS_PLAIN(0);
    __syncthreads();
    for (int it = 0; it < nIter; ++it) {
        const int buf = it & 1;
        if (it + 1 < nIter) LDG_TILES((it + 1) * 32);
        MMA_BODY(buf);
        if (it + 1 < nIter) STS_PLAIN(buf ^ 1);
        __syncthreads();
    }

    float* Cz = C + (long)bz * sC;
    const float* Rz = HASRES ? (resid + (long)bz * sR) : nullptr;
#pragma unroll
    for (int mi = 0; mi < 4; mi++) {
        const long row0 = bm + wm * 64 + mi * 16 + g;
        const long row1 = row0 + 8;
        float br0 = 0.f, br1 = 0.f;
        if (!BIASCOL && bias) { br0 = bias[row0]; br1 = bias[row1]; }
#pragma unroll
        for (int ni = 0; ni < 4; ni++) {
            const long col = bn + wn * 32 + ni * 8 + 2 * t;
            float2 v0 = make_float2(c[mi][ni][0], c[mi][ni][1]);
            float2 v1 = make_float2(c[mi][ni][2], c[mi][ni][3]);
            if (BIASCOL) {
                const float bc0 = bias[col], bc1 = bias[col + 1];
                v0.x += bc0; v0.y += bc1; v1.x += bc0; v1.y += bc1;
            } else if (bias) {
                v0.x += br0; v0.y += br0; v1.x += br1; v1.y += br1;
            }
            v0.x *= alpha; v0.y *= alpha; v1.x *= alpha; v1.y *= alpha;
            if (HASRES) {
                float2 r0 = *reinterpret_cast<const float2*>(Rz + row0 * ldc + col);
                float2 r1 = *reinterpret_cast<const float2*>(Rz + row1 * ldc + col);
                v0.x += r0.x; v0.y += r0.y; v1.x += r1.x; v1.y += r1.y;
            }
            *reinterpret_cast<float2*>(Cz + row0 * ldc + col) = v0;
            *reinterpret_cast<float2*>(Cz + row1 * ldc + col) = v1;
        }
    }
}

// ---------------------------------------------------------------------------
// logits GEMM: attn_exp[n][m] = exp(l - m_tile), plus per-(row,tile) m,s stats
// A=qt (M=NSP), B=kt (N=NSP), K=NC
// ---------------------------------------------------------------------------
__global__ __launch_bounds__(256, 2)
void logits_gemm(const float* __restrict__ A, long sA, int lda,
                 const float* __restrict__ B, long sB, int ldb,
                 float* __restrict__ C, long sC, int ldc,
                 float* __restrict__ pm, float* __restrict__ ps)
{
    GEMM_PREAMBLE
    const float* gA = A + (long)bz * sA + (bm + rr) * lda + ii * 4;
    const float* gB = B + (long)bz * sB + (bn + rr) * ldb + ii * 4;

    const int nIter = NC >> 5;   // 8
    LDG_TILES(0);
    STS_PLAIN(0);
    __syncthreads();
    for (int it = 0; it < nIter; ++it) {
        const int buf = it & 1;
        if (it + 1 < nIter) LDG_TILES((it + 1) * 32);
        MMA_BODY(buf);
        if (it + 1 < nIter) STS_PLAIN(buf ^ 1);
        __syncthreads();
    }

    // -------- per-row (M-dim) tile stats: max + sumexp over 128 cols --------
    float* smm = sm;          // [128][4]
    float* sms = sm + 512;    // [128][4]

#pragma unroll
    for (int mi = 0; mi < 4; mi++)
#pragma unroll
        for (int h = 0; h < 2; h++) {
            float m0 = -1e30f;
#pragma unroll
            for (int ni = 0; ni < 4; ni++)
                m0 = fmaxf(m0, fmaxf(c[mi][ni][2 * h], c[mi][ni][2 * h + 1]));
            m0 = fmaxf(m0, __shfl_xor_sync(0xffffffff, m0, 1));
            m0 = fmaxf(m0, __shfl_xor_sync(0xffffffff, m0, 2));
            if (t == 0) smm[(wm * 64 + mi * 16 + g + 8 * h) * 4 + wn] = m0;
        }
    __syncthreads();

    float mt[4][2];
#pragma unroll
    for (int mi = 0; mi < 4; mi++)
#pragma unroll
        for (int h = 0; h < 2; h++) {
            const int R = wm * 64 + mi * 16 + g + 8 * h;
            float m0 = fmaxf(fmaxf(smm[R * 4 + 0], smm[R * 4 + 1]),
                             fmaxf(smm[R * 4 + 2], smm[R * 4 + 3]));
            mt[mi][h] = m0;
            float s0 = 0.f;
#pragma unroll
            for (int ni = 0; ni < 4; ni++) {
                float e0 = __expf(c[mi][ni][2 * h]     - m0);
                float e1 = __expf(c[mi][ni][2 * h + 1] - m0);
                c[mi][ni][2 * h]     = e0;
                c[mi][ni][2 * h + 1] = e1;
                s0 += e0 + e1;
            }
            s0 += __shfl_xor_sync(0xffffffff, s0, 1);
            s0 += __shfl_xor_sync(0xffffffff, s0, 2);
            if (t == 0) sms[R * 4 + wn] = s0;
        }
    __syncthreads();

    if (wn == 0 && t == 0) {
#pragma unroll
        for (int mi = 0; mi < 4; mi++)
#pragma unroll
            for (int h = 0; h < 2; h++) {
                const int R = wm * 64 + mi * 16 + g + 8 * h;
                const float s0 = sms[R * 4 + 0] + sms[R * 4 + 1]
                               + sms[R * 4 + 2] + sms[R * 4 + 3];
                const long idx = ((long)bz * NSP + bm + R) * NTIL + blockIdx.x;
                pm[idx] = mt[mi][h];
                ps[idx] = s0;
            }
    }

    // -------- store exp'd values --------
    float* Cz = C + (long)bz * sC;
#pragma unroll
    for (int mi = 0; mi < 4; mi++) {
        const long row0 = bm + wm * 64 + mi * 16 + g;
        const long row1 = row0 + 8;
#pragma unroll
        for (int ni = 0; ni < 4; ni++) {
            const long col = bn + wn * 32 + ni * 8 + 2 * t;
            *reinterpret_cast<float2*>(Cz + row0 * ldc + col) =
                make_float2(c[mi][ni][0], c[mi][ni][1]);
            *reinterpret_cast<float2*>(Cz + row1 * ldc + col) =
                make_float2(c[mi][ni][2], c[mi][ni][3]);
        }
    }
}

// ---------------------------------------------------------------------------
// combine: per row, m = max_t m_t;  s = sum_t s_t*exp(m_t-m);
//          scale[t] = exp(m_t - m) / s
// one warp per row
// ---------------------------------------------------------------------------
__global__ void combine_kernel(const float* __restrict__ pm,
                               const float* __restrict__ ps,
                               float* __restrict__ sc)
{
    const long row = (long)blockIdx.x * 8 + (threadIdx.x >> 5);
    const int lane = threadIdx.x & 31;
    const float m_t = pm[row * NTIL + lane];
    const float s_t = ps[row * NTIL + lane];
    float m = m_t;
#pragma unroll
    for (int off = 16; off > 0; off >>= 1)
        m = fmaxf(m, __shfl_xor_sync(0xffffffff, m, off));
    const float e = __expf(m_t - m);
    float s = s_t * e;
#pragma unroll
    for (int off = 16; off > 0; off >>= 1)
        s += __shfl_xor_sync(0xffffffff, s, off);
    sc[row * NTIL + lane] = e / s;
}

// ---------------------------------------------------------------------------
// PV GEMM: ot[n][o] = sum_m (attn_exp[n][m] * scale[n][m/128]) * v[o][m]
// ---------------------------------------------------------------------------
__global__ __launch_bounds__(256, 2)
void pv_gemm(const float* __restrict__ A, long sA, int lda,
             const float* __restrict__ B, long sB, int ldb,
             float* __restrict__ C, long sC, int ldc,
             const float* __restrict__ sc)
{
    GEMM_PREAMBLE
    const float* gA = A + (long)bz * sA + (bm + rr) * lda + ii * 4;
    const float* gB = B + (long)bz * sB + (bn + rr) * ldb + ii * 4;
    const float* scb = sc + ((long)bz * NSP + bm) * NTIL;

    const int nIter = NSP >> 5;   // 128
    LDG_TILES(0);
    STS_SCALED(0, 0);
    __syncthreads();
    for (int it = 0; it < nIter; ++it) {
        const int buf = it & 1;
        if (it + 1 < nIter) LDG_TILES((it + 1) * 32);
        MMA_BODY(buf);
        if (it + 1 < nIter) STS_SCALED(buf ^ 1, (it + 1) * 32);
        __syncthreads();
    }

    float* Cz = C + (long)bz * sC;
#pragma unroll
    for (int mi = 0; mi < 4; mi++) {
        const long row0 = bm + wm * 64 + mi * 16 + g;
        const long row1 = row0 + 8;
#pragma unroll
        for (int ni = 0; ni < 4; ni++) {
            const long col = bn + wn * 32 + ni * 8 + 2 * t;
            *reinterpret_cast<float2*>(Cz + row0 * ldc + col) =
                make_float2(c[mi][ni][0], c[mi][ni][1]);
            *reinterpret_cast<float2*>(Cz + row1 * ldc + col) =
                make_float2(c[mi][ni][2], c[mi][ni][3]);
        }
    }
}

// ---------------------------------------------------------------------------
extern "C" void kernel_launch(void* const* d_in, const int* in_sizes, int n_in,
                              void* d_out, int out_size)
{
    const float* x   = (const float*)d_in[0];
    const float* gnw = (const float*)d_in[1];
    const float* gnb = (const float*)d_in[2];
    const float* wq  = (const float*)d_in[3];
    const float* bq  = (const float*)d_in[4];
    const float* wk  = (const float*)d_in[5];
    const float* bk  = (const float*)d_in[6];
    const float* wv  = (const float*)d_in[7];
    const float* bv  = (const float*)d_in[8];
    const float* wp  = (const float*)d_in[9];
    const float* bp  = (const float*)d_in[10];
    float* out = (float*)d_out;

    float *ht, *qt, *kt, *v, *ot, *attn, *stat, *pm, *ps, *sc;
    cudaGetSymbolAddress((void**)&ht,   g_ht);
    cudaGetSymbolAddress((void**)&qt,   g_qt);
    cudaGetSymbolAddress((void**)&kt,   g_kt);
    cudaGetSymbolAddress((void**)&v,    g_v);
    cudaGetSymbolAddress((void**)&ot,   g_ot);
    cudaGetSymbolAddress((void**)&attn, g_attn);
    cudaGetSymbolAddress((void**)&stat, g_stat);
    cudaGetSymbolAddress((void**)&pm,   g_pm);
    cudaGetSymbolAddress((void**)&ps,   g_ps);
    cudaGetSymbolAddress((void**)&sc,   g_sc);

    const long sCN = (long)NC * NSP;
    const long sNN = (long)NSP * NSP;
    const int SMEM = 4 * TSZ * 4;   // 73728 bytes

    cudaFuncSetAttribute(mma_gemm<1, 0>, cudaFuncAttributeMaxDynamicSharedMemorySize, SMEM);
    cudaFuncSetAttribute(mma_gemm<0, 0>, cudaFuncAttributeMaxDynamicSharedMemorySize, SMEM);
    cudaFuncSetAttribute(mma_gemm<0, 1>, cudaFuncAttributeMaxDynamicSharedMemorySize, SMEM);
    cudaFuncSetAttribute(logits_gemm, cudaFuncAttributeMaxDynamicSharedMemorySize, SMEM);
    cudaFuncSetAttribute(pv_gemm, cudaFuncAttributeMaxDynamicSharedMemorySize, SMEM);

    // 1) GroupNorm -> ht[b][n][c]
    gn_stats<<<NB * NGRP, 256>>>(x, stat);
    gn_apply<<<dim3(NC / 32, NSP / 32, NB), dim3(32, 8)>>>(x, gnw, gnb, stat, ht);

    // 2) projections
    dim3 gQ(NC / 128, NSP / 128, NB);       // 2 x 32 x 2
    mma_gemm<1, 0><<<gQ, 256, SMEM>>>(ht, sCN, NC, wq, 0, NC, qt, sCN, NC,
                                      NC, 0.0625f, bq, nullptr, 0);
    mma_gemm<1, 0><<<gQ, 256, SMEM>>>(ht, sCN, NC, wk, 0, NC, kt, sCN, NC,
                                      NC, 1.f, bk, nullptr, 0);
    dim3 gV(NSP / 128, NC / 128, NB);       // 32 x 2 x 2
    mma_gemm<0, 0><<<gV, 256, SMEM>>>(wv, 0, NC, ht, sCN, NC, v, sCN, NSP,
                                      NC, 1.f, bv, nullptr, 0);

    // 3) logits GEMM with fused exp + tile stats
    dim3 gS(NSP / 128, NSP / 128, NB);      // 32 x 32 x 2
    logits_gemm<<<gS, 256, SMEM>>>(qt, sCN, NC, kt, sCN, NC, attn, sNN, NSP,
                                   pm, ps);

    // 4) combine stats -> per (row, tile) scale
    combine_kernel<<<NB * NSP / 8, 256>>>(pm, ps, sc);

    // 5) PV with fused scaling
    dim3 gO(NC / 128, NSP / 128, NB);       // 2 x 32 x 2
    pv_gemm<<<gO, 256, SMEM>>>(attn, sNN, NSP, v, sCN, NSP, ot, sCN, NC, sc);

    // 6) out-projection + residual
    mma_gemm<0, 1><<<gV, 256, SMEM>>>(wp, 0, NC, ot, sCN, NC, out, sCN, NSP,
                                      NC, 1.f, bp, x, sCN);
}

// round 9
// speedup vs baseline: 1.6469x; 1.4165x over previous
#include <cuda_runtime.h>
#include <cuda_fp16.h>
#include <cstdint>

#define NB   2
#define NC   256
#define NSP  4096
#define NGRP 32
#define CPG  8
#define NTIL 32

// ---------------- scratch (no allocation allowed) ----------------
__device__ __half g_ht  [(size_t)NB * NC * NSP];   // hT  [b][n][c]
__device__ __half g_qt  [(size_t)NB * NC * NSP];   // qT  [b][n][o] (pre-scaled 1/16)
__device__ __half g_kt  [(size_t)NB * NC * NSP];   // kT  [b][n][o]
__device__ __half g_v   [(size_t)NB * NC * NSP];   // v   [b][o][m]
__device__ __half g_ot  [(size_t)NB * NC * NSP];   // outT[b][n][o]
__device__ __half g_attn[(size_t)NB * NSP * NSP];  // exp(l - m_tile), 64 MiB
__device__ float  g_stat[NB * NGRP * 2];
__device__ float  g_pm  [(size_t)NB * NSP * NTIL];
__device__ float  g_ps  [(size_t)NB * NSP * NTIL];
__device__ float  g_sce [(size_t)NB * NSP * NTIL]; // exp(m_t - m)
__device__ float  g_sci [(size_t)NB * NSP];        // 1 / s_global

// ---------------- helpers ----------------
__device__ __forceinline__ uint32_t f2h2(float x, float y) {
    __half2 h = __floats2half2_rn(x, y);
    return *reinterpret_cast<uint32_t*>(&h);
}

__device__ __forceinline__ void mma16(float* c, const uint32_t* a, const uint32_t* b) {
    asm volatile(
        "mma.sync.aligned.m16n8k16.row.col.f32.f16.f16.f32 "
        "{%0,%1,%2,%3}, {%4,%5,%6,%7}, {%8,%9}, {%0,%1,%2,%3};\n"
        : "+f"(c[0]), "+f"(c[1]), "+f"(c[2]), "+f"(c[3])
        : "r"(a[0]), "r"(a[1]), "r"(a[2]), "r"(a[3]),
          "r"(b[0]), "r"(b[1]));
}

// ---------------- GroupNorm stats ----------------
__global__ void gn_stats(const float* __restrict__ x, float* __restrict__ stat)
{
    const int b = blockIdx.x >> 5;
    const int g = blockIdx.x & 31;
    const float* xp = x + ((long)b * NC + (long)g * CPG) * NSP;
    const int tid = threadIdx.x;
    const int TOT = CPG * NSP;

    float s = 0.f, ss = 0.f;
    for (int i = tid * 4; i < TOT; i += 1024) {
        float4 v = *reinterpret_cast<const float4*>(xp + i);
        s  += v.x + v.y + v.z + v.w;
        ss += v.x * v.x + v.y * v.y + v.z * v.z + v.w * v.w;
    }
    __shared__ float rs[256], rss[256];
    rs[tid] = s; rss[tid] = ss;
    __syncthreads();
    for (int off = 128; off > 0; off >>= 1) {
        if (tid < off) { rs[tid] += rs[tid + off]; rss[tid] += rss[tid + off]; }
        __syncthreads();
    }
    if (tid == 0) {
        float mean = rs[0] / (float)TOT;
        float var  = rss[0] / (float)TOT - mean * mean;
        stat[blockIdx.x * 2 + 0] = mean;
        stat[blockIdx.x * 2 + 1] = rsqrtf(var + 1e-5f);
    }
}

// ---------------- GroupNorm apply + transpose -> fp16 ht ----------------
__global__ void gn_apply(const float* __restrict__ x,
                         const float* __restrict__ w,
                         const float* __restrict__ bb,
                         const float* __restrict__ stat,
                         __half* __restrict__ ht)
{
    __shared__ float t[32][33];
    const int b  = blockIdx.z;
    const int c0 = blockIdx.x * 32;
    const int n0 = blockIdx.y * 32;
    const int tx = threadIdx.x, ty = threadIdx.y;
    const float* xb = x  + (long)b * NC * NSP;
    __half*      hb = ht + (long)b * NSP * NC;

#pragma unroll
    for (int j = 0; j < 4; j++) {
        const int c = c0 + ty + j * 8;
        const int g = c >> 3;
        const float mean = stat[(b * NGRP + g) * 2 + 0];
        const float inv  = stat[(b * NGRP + g) * 2 + 1];
        const float wc = w[c] * inv;
        const float bc = bb[c] - mean * wc;
        t[ty + j * 8][tx] = xb[(long)c * NSP + n0 + tx] * wc + bc;
    }
    __syncthreads();
#pragma unroll
    for (int j = 0; j < 4; j++) {
        const int n = n0 + ty + j * 8;
        hb[(long)n * NC + c0 + tx] = __float2half_rn(t[tx][ty + j * 8]);
    }
}

// =============== fp16 GEMM mainloop pieces ===============
#define TSZH 5120   // halves per buffer: 128 rows * 40

#define GEMM_PREAMBLE \
    extern __shared__ __half smh[]; \
    const int tid = threadIdx.x; \
    const int wid = tid >> 5, lane = tid & 31; \
    const int wm = wid >> 2, wn = wid & 3; \
    const int g = lane >> 2, t = lane & 3; \
    const int bz = blockIdx.z; \
    const long bm = (long)blockIdx.y * 128; \
    const long bn = (long)blockIdx.x * 128; \
    const int rr2 = tid >> 2, ii2 = tid & 3; \
    float c[4][4][4]; \
    _Pragma("unroll") for (int mi = 0; mi < 4; mi++) \
    _Pragma("unroll") for (int ni = 0; ni < 4; ni++) \
    _Pragma("unroll") for (int j = 0; j < 4; j++) c[mi][ni][j] = 0.f; \
    uint4 ua[2], ub[2];

#define LDG_H(dst, base, k0, ld) do { \
    dst[0] = *reinterpret_cast<const uint4*>((base) + (long)(k0)); \
    dst[1] = *reinterpret_cast<const uint4*>((base) + (long)(k0) + 64L * (ld)); \
} while (0)

#define LDG_F(dst, base, k0, ld) do { \
    float4 p0_ = *reinterpret_cast<const float4*>((base) + (long)(k0)); \
    float4 p1_ = *reinterpret_cast<const float4*>((base) + (long)(k0) + 4); \
    dst[0] = make_uint4(f2h2(p0_.x, p0_.y), f2h2(p0_.z, p0_.w), \
                        f2h2(p1_.x, p1_.y), f2h2(p1_.z, p1_.w)); \
    p0_ = *reinterpret_cast<const float4*>((base) + (long)(k0) + 64L * (ld)); \
    p1_ = *reinterpret_cast<const float4*>((base) + (long)(k0) + 64L * (ld) + 4); \
    dst[1] = make_uint4(f2h2(p0_.x, p0_.y), f2h2(p0_.z, p0_.w), \
                        f2h2(p1_.x, p1_.y), f2h2(p1_.z, p1_.w)); \
} while (0)

#define STS_AB(buf) do { \
    __half* As_ = smh + (buf) * TSZH + rr2 * 40 + ii2 * 8; \
    __half* Bs_ = smh + 2 * TSZH + (buf) * TSZH + rr2 * 40 + ii2 * 8; \
    *reinterpret_cast<uint4*>(As_)            = ua[0]; \
    *reinterpret_cast<uint4*>(As_ + 64 * 40)  = ua[1]; \
    *reinterpret_cast<uint4*>(Bs_)            = ub[0]; \
    *reinterpret_cast<uint4*>(Bs_ + 64 * 40)  = ub[1]; \
} while (0)

#define MMA_BODY16(buf) do { \
    const __half* As = smh + (buf) * TSZH + (wm * 64 + g) * 40 + 2 * t; \
    const __half* Bs = smh + 2 * TSZH + (buf) * TSZH + (wn * 32 + g) * 40 + 2 * t; \
    _Pragma("unroll") for (int kk = 0; kk < 32; kk += 16) { \
        uint32_t a[4][4], b[4][2]; \
        _Pragma("unroll") for (int mi = 0; mi < 4; mi++) { \
            const __half* ap = As + mi * 16 * 40 + kk; \
            a[mi][0] = *reinterpret_cast<const uint32_t*>(ap); \
            a[mi][1] = *reinterpret_cast<const uint32_t*>(ap + 8 * 40); \
            a[mi][2] = *reinterpret_cast<const uint32_t*>(ap + 8); \
            a[mi][3] = *reinterpret_cast<const uint32_t*>(ap + 8 * 40 + 8); } \
        _Pragma("unroll") for (int ni = 0; ni < 4; ni++) { \
            const __half* bp = Bs + ni * 8 * 40 + kk; \
            b[ni][0] = *reinterpret_cast<const uint32_t*>(bp); \
            b[ni][1] = *reinterpret_cast<const uint32_t*>(bp + 8); } \
        _Pragma("unroll") for (int mi = 0; mi < 4; mi++) \
        _Pragma("unroll") for (int ni = 0; ni < 4; ni++) \
            mma16(c[mi][ni], a[mi], b[ni]); \
    } \
} while (0)

// ---------------------------------------------------------------------------
// generic GEMM: AH/BH = operand dtype (1=half, 0=float src converted),
// OUTH: 1 = half output (no residual), 0 = float output (+resid)
// C[m,n] = (sum_k A[m,k]*B[n,k] + bias) * alpha (+ resid)
// ---------------------------------------------------------------------------
template<int AH, int BH, int BIASCOL, int HASRES, int OUTH>
__global__ __launch_bounds__(256, 2)
void hgemm(const void* Av, long sA, int lda,
           const void* Bv, long sB, int ldb,
           void* Cv, long sC, int ldc,
           int K, float alpha,
           const float* __restrict__ bias,
           const float* __restrict__ resid, long sR)
{
    GEMM_PREAMBLE
    const __half* gAh = AH ? ((const __half*)Av + (long)bz * sA + (bm + rr2) * (long)lda + ii2 * 8) : nullptr;
    const float*  gAf = AH ? nullptr : ((const float*)Av + (long)bz * sA + (bm + rr2) * (long)lda + ii2 * 8);
    const __half* gBh = BH ? ((const __half*)Bv + (long)bz * sB + (bn + rr2) * (long)ldb + ii2 * 8) : nullptr;
    const float*  gBf = BH ? nullptr : ((const float*)Bv + (long)bz * sB + (bn + rr2) * (long)ldb + ii2 * 8);

#define LDG_BOTH(k0) do { \
    if (AH) LDG_H(ua, gAh, k0, lda); else LDG_F(ua, gAf, k0, lda); \
    if (BH) LDG_H(ub, gBh, k0, ldb); else LDG_F(ub, gBf, k0, ldb); \
} while (0)

    const int nIter = K >> 5;
    LDG_BOTH(0);
    STS_AB(0);
    __syncthreads();
    for (int it = 0; it < nIter; ++it) {
        const int buf = it & 1;
        if (it + 1 < nIter) LDG_BOTH((it + 1) * 32);
        MMA_BODY16(buf);
        if (it + 1 < nIter) STS_AB(buf ^ 1);
        __syncthreads();
    }
#undef LDG_BOTH

#pragma unroll
    for (int mi = 0; mi < 4; mi++) {
        const long row0 = bm + wm * 64 + mi * 16 + g;
        const long row1 = row0 + 8;
        float br0 = 0.f, br1 = 0.f;
        if (!BIASCOL && bias) { br0 = bias[row0]; br1 = bias[row1]; }
#pragma unroll
        for (int ni = 0; ni < 4; ni++) {
            const long col = bn + wn * 32 + ni * 8 + 2 * t;
            float2 v0 = make_float2(c[mi][ni][0], c[mi][ni][1]);
            float2 v1 = make_float2(c[mi][ni][2], c[mi][ni][3]);
            if (BIASCOL) {
                const float bc0 = bias[col], bc1 = bias[col + 1];
                v0.x += bc0; v0.y += bc1; v1.x += bc0; v1.y += bc1;
            } else if (bias) {
                v0.x += br0; v0.y += br0; v1.x += br1; v1.y += br1;
            }
            v0.x *= alpha; v0.y *= alpha; v1.x *= alpha; v1.y *= alpha;
            if (OUTH) {
                __half* Cz = (__half*)Cv + (long)bz * sC;
                *reinterpret_cast<__half2*>(Cz + row0 * ldc + col) = __floats2half2_rn(v0.x, v0.y);
                *reinterpret_cast<__half2*>(Cz + row1 * ldc + col) = __floats2half2_rn(v1.x, v1.y);
            } else {
                float* Cz = (float*)Cv + (long)bz * sC;
                if (HASRES) {
                    const float* Rz = resid + (long)bz * sR;
                    float2 r0 = *reinterpret_cast<const float2*>(Rz + row0 * ldc + col);
                    float2 r1 = *reinterpret_cast<const float2*>(Rz + row1 * ldc + col);
                    v0.x += r0.x; v0.y += r0.y; v1.x += r1.x; v1.y += r1.y;
                }
                *reinterpret_cast<float2*>(Cz + row0 * ldc + col) = v0;
                *reinterpret_cast<float2*>(Cz + row1 * ldc + col) = v1;
            }
        }
    }
}

// ---------------------------------------------------------------------------
// logits GEMM: A=qt(h), B=kt(h); writes exp(l - m_tile) as half + (m,s) stats
// ---------------------------------------------------------------------------
__global__ __launch_bounds__(256, 2)
void logits_gemm(const __half* __restrict__ A, long sA, int lda,
                 const __half* __restrict__ B, long sB, int ldb,
                 __half* __restrict__ C, long sC, int ldc,
                 float* __restrict__ pm, float* __restrict__ ps)
{
    GEMM_PREAMBLE
    const __half* gAh = A + (long)bz * sA + (bm + rr2) * (long)lda + ii2 * 8;
    const __half* gBh = B + (long)bz * sB + (bn + rr2) * (long)ldb + ii2 * 8;

    const int nIter = NC >> 5;   // 8
    LDG_H(ua, gAh, 0, lda); LDG_H(ub, gBh, 0, ldb);
    STS_AB(0);
    __syncthreads();
    for (int it = 0; it < nIter; ++it) {
        const int buf = it & 1;
        if (it + 1 < nIter) { LDG_H(ua, gAh, (it + 1) * 32, lda); LDG_H(ub, gBh, (it + 1) * 32, ldb); }
        MMA_BODY16(buf);
        if (it + 1 < nIter) STS_AB(buf ^ 1);
        __syncthreads();
    }

    float* smf = reinterpret_cast<float*>(smh);
    float* smm = smf;          // [128][4]
    float* sms = smf + 512;    // [128][4]

#pragma unroll
    for (int mi = 0; mi < 4; mi++)
#pragma unroll
        for (int h = 0; h < 2; h++) {
            float m0 = -1e30f;
#pragma unroll
            for (int ni = 0; ni < 4; ni++)
                m0 = fmaxf(m0, fmaxf(c[mi][ni][2 * h], c[mi][ni][2 * h + 1]));
            m0 = fmaxf(m0, __shfl_xor_sync(0xffffffff, m0, 1));
            m0 = fmaxf(m0, __shfl_xor_sync(0xffffffff, m0, 2));
            if (t == 0) smm[(wm * 64 + mi * 16 + g + 8 * h) * 4 + wn] = m0;
        }
    __syncthreads();

    float mt[4][2];
#pragma unroll
    for (int mi = 0; mi < 4; mi++)
#pragma unroll
        for (int h = 0; h < 2; h++) {
            const int R = wm * 64 + mi * 16 + g + 8 * h;
            float m0 = fmaxf(fmaxf(smm[R * 4 + 0], smm[R * 4 + 1]),
                             fmaxf(smm[R * 4 + 2], smm[R * 4 + 3]));
            mt[mi][h] = m0;
            float s0 = 0.f;
#pragma unroll
            for (int ni = 0; ni < 4; ni++) {
                float e0 = __expf(c[mi][ni][2 * h]     - m0);
                float e1 = __expf(c[mi][ni][2 * h + 1] - m0);
                c[mi][ni][2 * h]     = e0;
                c[mi][ni][2 * h + 1] = e1;
                s0 += e0 + e1;
            }
            s0 += __shfl_xor_sync(0xffffffff, s0, 1);
            s0 += __shfl_xor_sync(0xffffffff, s0, 2);
            if (t == 0) sms[R * 4 + wn] = s0;
        }
    __syncthreads();

    if (wn == 0 && t == 0) {
#pragma unroll
        for (int mi = 0; mi < 4; mi++)
#pragma unroll
            for (int h = 0; h < 2; h++) {
                const int R = wm * 64 + mi * 16 + g + 8 * h;
                const float s0 = sms[R * 4 + 0] + sms[R * 4 + 1]
                               + sms[R * 4 + 2] + sms[R * 4 + 3];
                const long idx = ((long)bz * NSP + bm + R) * NTIL + blockIdx.x;
                pm[idx] = mt[mi][h];
                ps[idx] = s0;
            }
    }

    __half* Cz = C + (long)bz * sC;
#pragma unroll
    for (int mi = 0; mi < 4; mi++) {
        const long row0 = bm + wm * 64 + mi * 16 + g;
        const long row1 = row0 + 8;
#pragma unroll
        for (int ni = 0; ni < 4; ni++) {
            const long col = bn + wn * 32 + ni * 8 + 2 * t;
            *reinterpret_cast<__half2*>(Cz + row0 * ldc + col) =
                __floats2half2_rn(c[mi][ni][0], c[mi][ni][1]);
            *reinterpret_cast<__half2*>(Cz + row1 * ldc + col) =
                __floats2half2_rn(c[mi][ni][2], c[mi][ni][3]);
        }
    }
}

// ---------------------------------------------------------------------------
// combine: e_t = exp(m_t - m); s = sum_t s_t*e_t; sce=e_t, sci=1/s
// ---------------------------------------------------------------------------
__global__ void combine_kernel(const float* __restrict__ pm,
                               const float* __restrict__ ps,
                               float* __restrict__ sce,
                               float* __restrict__ sci)
{
    const long row = (long)blockIdx.x * 8 + (threadIdx.x >> 5);
    const int lane = threadIdx.x & 31;
    const float m_t = pm[row * NTIL + lane];
    const float s_t = ps[row * NTIL + lane];
    float m = m_t;
#pragma unroll
    for (int off = 16; off > 0; off >>= 1)
        m = fmaxf(m, __shfl_xor_sync(0xffffffff, m, off));
    const float e = __expf(m_t - m);
    float s = s_t * e;
#pragma unroll
    for (int off = 16; off > 0; off >>= 1)
        s += __shfl_xor_sync(0xffffffff, s, off);
    sce[row * NTIL + lane] = e;
    if (lane == 0) sci[row] = 1.f / s;
}

// ---------------------------------------------------------------------------
// PV GEMM: ot[n][o] = (1/s_n) * sum_m (attn_exp[n][m]*e_t) * v[o][m]
// ---------------------------------------------------------------------------
__global__ __launch_bounds__(256, 2)
void pv_gemm(const __half* __restrict__ A, long sA, int lda,
             const __half* __restrict__ B, long sB, int ldb,
             __half* __restrict__ C, long sC, int ldc,
             const float* __restrict__ sce,
             const float* __restrict__ sci)
{
    GEMM_PREAMBLE
    const __half* gAh = A + (long)bz * sA + (bm + rr2) * (long)lda + ii2 * 8;
    const __half* gBh = B + (long)bz * sB + (bn + rr2) * (long)ldb + ii2 * 8;
    const float* scb = sce + ((long)bz * NSP + bm) * NTIL;

#define LDG_PV(k0) do { \
    LDG_H(ua, gAh, k0, lda); LDG_H(ub, gBh, k0, ldb); \
    const int tm_ = (k0) >> 7; \
    __half2 F0 = __float2half2_rn(scb[rr2 * NTIL + tm_]); \
    __half2 F1 = __float2half2_rn(scb[(rr2 + 64) * NTIL + tm_]); \
    __half2* pa0 = reinterpret_cast<__half2*>(&ua[0]); \
    __half2* pa1 = reinterpret_cast<__half2*>(&ua[1]); \
    _Pragma("unroll") for (int q_ = 0; q_ < 4; q_++) { \
        pa0[q_] = __hmul2(pa0[q_], F0); pa1[q_] = __hmul2(pa1[q_], F1); } \
} while (0)

    const int nIter = NSP >> 5;   // 128
    LDG_PV(0);
    STS_AB(0);
    __syncthreads();
    for (int it = 0; it < nIter; ++it) {
        const int buf = it & 1;
        if (it + 1 < nIter) LDG_PV((it + 1) * 32);
        MMA_BODY16(buf);
        if (it + 1 < nIter) STS_AB(buf ^ 1);
        __syncthreads();
    }
#undef LDG_PV

    __half* Cz = C + (long)bz * sC;
    const float* inv = sci + (long)bz * NSP;
#pragma unroll
    for (int mi = 0; mi < 4; mi++) {
        const long row0 = bm + wm * 64 + mi * 16 + g;
        const long row1 = row0 + 8;
        const float i0 = inv[row0], i1 = inv[row1];
#pragma unroll
        for (int ni = 0; ni < 4; ni++) {
            const long col = bn + wn * 32 + ni * 8 + 2 * t;
            *reinterpret_cast<__half2*>(Cz + row0 * ldc + col) =
                __floats2half2_rn(c[mi][ni][0] * i0, c[mi][ni][1] * i0);
            *reinterpret_cast<__half2*>(Cz + row1 * ldc + col) =
                __floats2half2_rn(c[mi][ni][2] * i1, c[mi][ni][3] * i1);
        }
    }
}

// ---------------------------------------------------------------------------
extern "C" void kernel_launch(void* const* d_in, const int* in_sizes, int n_in,
                              void* d_out, int out_size)
{
    const float* x   = (const float*)d_in[0];
    const float* gnw = (const float*)d_in[1];
    const float* gnb = (const float*)d_in[2];
    const float* wq  = (const float*)d_in[3];
    const float* bq  = (const float*)d_in[4];
    const float* wk  = (const float*)d_in[5];
    const float* bk  = (const float*)d_in[6];
    const float* wv  = (const float*)d_in[7];
    const float* bv  = (const float*)d_in[8];
    const float* wp  = (const float*)d_in[9];
    const float* bp  = (const float*)d_in[10];
    float* out = (float*)d_out;

    __half *ht, *qt, *kt, *v, *ot, *attn;
    float *stat, *pm, *ps, *sce, *sci;
    cudaGetSymbolAddress((void**)&ht,   g_ht);
    cudaGetSymbolAddress((void**)&qt,   g_qt);
    cudaGetSymbolAddress((void**)&kt,   g_kt);
    cudaGetSymbolAddress((void**)&v,    g_v);
    cudaGetSymbolAddress((void**)&ot,   g_ot);
    cudaGetSymbolAddress((void**)&attn, g_attn);
    cudaGetSymbolAddress((void**)&stat, g_stat);
    cudaGetSymbolAddress((void**)&pm,   g_pm);
    cudaGetSymbolAddress((void**)&ps,   g_ps);
    cudaGetSymbolAddress((void**)&sce,  g_sce);
    cudaGetSymbolAddress((void**)&sci,  g_sci);

    const long sCN = (long)NC * NSP;
    const long sNN = (long)NSP * NSP;
    const int SMEM = 4 * TSZH * 2;   // 40960 bytes

    // 1) GroupNorm -> ht (fp16)
    gn_stats<<<NB * NGRP, 256>>>(x, stat);
    gn_apply<<<dim3(NC / 32, NSP / 32, NB), dim3(32, 8)>>>(x, gnw, gnb, stat, ht);

    // 2) projections
    dim3 gQ(NC / 128, NSP / 128, NB);       // 2 x 32 x 2
    hgemm<1, 0, 1, 0, 1><<<gQ, 256, SMEM>>>(ht, sCN, NC, wq, 0, NC, qt, sCN, NC,
                                            NC, 0.0625f, bq, nullptr, 0);
    hgemm<1, 0, 1, 0, 1><<<gQ, 256, SMEM>>>(ht, sCN, NC, wk, 0, NC, kt, sCN, NC,
                                            NC, 1.f, bk, nullptr, 0);
    dim3 gV(NSP / 128, NC / 128, NB);       // 32 x 2 x 2
    hgemm<0, 1, 0, 0, 1><<<gV, 256, SMEM>>>(wv, 0, NC, ht, sCN, NC, v, sCN, NSP,
                                            NC, 1.f, bv, nullptr, 0);

    // 3) logits with fused exp + tile stats
    dim3 gS(NSP / 128, NSP / 128, NB);      // 32 x 32 x 2
    logits_gemm<<<gS, 256, SMEM>>>(qt, sCN, NC, kt, sCN, NC, attn, sNN, NSP,
                                   pm, ps);

    // 4) combine
    combine_kernel<<<NB * NSP / 8, 256>>>(pm, ps, sce, sci);

    // 5) PV with fused e_t scaling + 1/s epilogue
    dim3 gO(NC / 128, NSP / 128, NB);       // 2 x 32 x 2
    pv_gemm<<<gO, 256, SMEM>>>(attn, sNN, NSP, v, sCN, NSP, ot, sCN, NC, sce, sci);

    // 6) out-projection + residual (fp32 out)
    hgemm<0, 1, 0, 1, 0><<<gV, 256, SMEM>>>(wp, 0, NC, ot, sCN, NC, out, sCN, NSP,
                                            NC, 1.f, bp, x, sCN);
}

// round 10
// speedup vs baseline: 1.8034x; 1.0950x over previous
#include <cuda_runtime.h>
#include <cuda_fp16.h>
#include <cstdint>

#define NB   2
#define NC   256
#define NSP  4096
#define NGRP 32
#define CPG  8
#define NTIL 32
#define KSPLIT 4

// ---------------- scratch (no allocation allowed) ----------------
__device__ __half g_ht  [(size_t)NB * NC * NSP];
__device__ __half g_qt  [(size_t)NB * NC * NSP];
__device__ __half g_kt  [(size_t)NB * NC * NSP];
__device__ __half g_v   [(size_t)NB * NC * NSP];
__device__ __half g_ot  [(size_t)NB * NC * NSP];
__device__ __half g_attn[(size_t)NB * NSP * NSP];          // 64 MiB
__device__ float  g_otp [(size_t)NB * KSPLIT * NC * NSP];  // 32 MiB fp32 partials
__device__ float  g_stat[NB * NGRP * 2];
__device__ float  g_pm  [(size_t)NB * NSP * NTIL];
__device__ float  g_ps  [(size_t)NB * NSP * NTIL];
__device__ float  g_sce [(size_t)NB * NSP * NTIL];
__device__ float  g_sci [(size_t)NB * NSP];

// ---------------- helpers ----------------
__device__ __forceinline__ uint32_t f2h2(float x, float y) {
    __half2 h = __floats2half2_rn(x, y);
    return *reinterpret_cast<uint32_t*>(&h);
}

__device__ __forceinline__ void mma16(float* c, const uint32_t* a, const uint32_t* b) {
    asm volatile(
        "mma.sync.aligned.m16n8k16.row.col.f32.f16.f16.f32 "
        "{%0,%1,%2,%3}, {%4,%5,%6,%7}, {%8,%9}, {%0,%1,%2,%3};\n"
        : "+f"(c[0]), "+f"(c[1]), "+f"(c[2]), "+f"(c[3])
        : "r"(a[0]), "r"(a[1]), "r"(a[2]), "r"(a[3]),
          "r"(b[0]), "r"(b[1]));
}

// ---------------- GroupNorm stats ----------------
__global__ void gn_stats(const float* __restrict__ x, float* __restrict__ stat)
{
    const int b = blockIdx.x >> 5;
    const int g = blockIdx.x & 31;
    const float* xp = x + ((long)b * NC + (long)g * CPG) * NSP;
    const int tid = threadIdx.x;
    const int TOT = CPG * NSP;

    float s = 0.f, ss = 0.f;
    for (int i = tid * 4; i < TOT; i += 1024) {
        float4 v = *reinterpret_cast<const float4*>(xp + i);
        s  += v.x + v.y + v.z + v.w;
        ss += v.x * v.x + v.y * v.y + v.z * v.z + v.w * v.w;
    }
    __shared__ float rs[256], rss[256];
    rs[tid] = s; rss[tid] = ss;
    __syncthreads();
    for (int off = 128; off > 0; off >>= 1) {
        if (tid < off) { rs[tid] += rs[tid + off]; rss[tid] += rss[tid + off]; }
        __syncthreads();
    }
    if (tid == 0) {
        float mean = rs[0] / (float)TOT;
        float var  = rss[0] / (float)TOT - mean * mean;
        stat[blockIdx.x * 2 + 0] = mean;
        stat[blockIdx.x * 2 + 1] = rsqrtf(var + 1e-5f);
    }
}

// ---------------- GroupNorm apply + transpose -> fp16 ht ----------------
__global__ void gn_apply(const float* __restrict__ x,
                         const float* __restrict__ w,
                         const float* __restrict__ bb,
                         const float* __restrict__ stat,
                         __half* __restrict__ ht)
{
    __shared__ float t[32][33];
    const int b  = blockIdx.z;
    const int c0 = blockIdx.x * 32;
    const int n0 = blockIdx.y * 32;
    const int tx = threadIdx.x, ty = threadIdx.y;
    const float* xb = x  + (long)b * NC * NSP;
    __half*      hb = ht + (long)b * NSP * NC;

#pragma unroll
    for (int j = 0; j < 4; j++) {
        const int c = c0 + ty + j * 8;
        const int g = c >> 3;
        const float mean = stat[(b * NGRP + g) * 2 + 0];
        const float inv  = stat[(b * NGRP + g) * 2 + 1];
        const float wc = w[c] * inv;
        const float bc = bb[c] - mean * wc;
        t[ty + j * 8][tx] = xb[(long)c * NSP + n0 + tx] * wc + bc;
    }
    __syncthreads();
#pragma unroll
    for (int j = 0; j < 4; j++) {
        const int n = n0 + ty + j * 8;
        hb[(long)n * NC + c0 + tx] = __float2half_rn(t[tx][ty + j * 8]);
    }
}

// =============== fp16 GEMM mainloop pieces ===============
#define TSZH 5120

#define GEMM_PREAMBLE \
    extern __shared__ __half smh[]; \
    const int tid = threadIdx.x; \
    const int wid = tid >> 5, lane = tid & 31; \
    const int wm = wid >> 2, wn = wid & 3; \
    const int g = lane >> 2, t = lane & 3; \
    const int bz = blockIdx.z; \
    const long bm = (long)blockIdx.y * 128; \
    const long bn = (long)blockIdx.x * 128; \
    const int rr2 = tid >> 2, ii2 = tid & 3; \
    float c[4][4][4]; \
    _Pragma("unroll") for (int mi = 0; mi < 4; mi++) \
    _Pragma("unroll") for (int ni = 0; ni < 4; ni++) \
    _Pragma("unroll") for (int j = 0; j < 4; j++) c[mi][ni][j] = 0.f; \
    uint4 ua[2], ub[2];

#define LDG_H(dst, base, k0, ld) do { \
    dst[0] = *reinterpret_cast<const uint4*>((base) + (long)(k0)); \
    dst[1] = *reinterpret_cast<const uint4*>((base) + (long)(k0) + 64L * (ld)); \
} while (0)

#define LDG_F(dst, base, k0, ld) do { \
    float4 p0_ = *reinterpret_cast<const float4*>((base) + (long)(k0)); \
    float4 p1_ = *reinterpret_cast<const float4*>((base) + (long)(k0) + 4); \
    dst[0] = make_uint4(f2h2(p0_.x, p0_.y), f2h2(p0_.z, p0_.w), \
                        f2h2(p1_.x, p1_.y), f2h2(p1_.z, p1_.w)); \
    p0_ = *reinterpret_cast<const float4*>((base) + (long)(k0) + 64L * (ld)); \
    p1_ = *reinterpret_cast<const float4*>((base) + (long)(k0) + 64L * (ld) + 4); \
    dst[1] = make_uint4(f2h2(p0_.x, p0_.y), f2h2(p0_.z, p0_.w), \
                        f2h2(p1_.x, p1_.y), f2h2(p1_.z, p1_.w)); \
} while (0)

#define STS_AB(buf) do { \
    __half* As_ = smh + (buf) * TSZH + rr2 * 40 + ii2 * 8; \
    __half* Bs_ = smh + 2 * TSZH + (buf) * TSZH + rr2 * 40 + ii2 * 8; \
    *reinterpret_cast<uint4*>(As_)            = ua[0]; \
    *reinterpret_cast<uint4*>(As_ + 64 * 40)  = ua[1]; \
    *reinterpret_cast<uint4*>(Bs_)            = ub[0]; \
    *reinterpret_cast<uint4*>(Bs_ + 64 * 40)  = ub[1]; \
} while (0)

#define MMA_BODY16(buf) do { \
    const __half* As = smh + (buf) * TSZH + (wm * 64 + g) * 40 + 2 * t; \
    const __half* Bs = smh + 2 * TSZH + (buf) * TSZH + (wn * 32 + g) * 40 + 2 * t; \
    _Pragma("unroll") for (int kk = 0; kk < 32; kk += 16) { \
        uint32_t a[4][4], b[4][2]; \
        _Pragma("unroll") for (int mi = 0; mi < 4; mi++) { \
            const __half* ap = As + mi * 16 * 40 + kk; \
            a[mi][0] = *reinterpret_cast<const uint32_t*>(ap); \
            a[mi][1] = *reinterpret_cast<const uint32_t*>(ap + 8 * 40); \
            a[mi][2] = *reinterpret_cast<const uint32_t*>(ap + 8); \
            a[mi][3] = *reinterpret_cast<const uint32_t*>(ap + 8 * 40 + 8); } \
        _Pragma("unroll") for (int ni = 0; ni < 4; ni++) { \
            const __half* bp = Bs + ni * 8 * 40 + kk; \
            b[ni][0] = *reinterpret_cast<const uint32_t*>(bp); \
            b[ni][1] = *reinterpret_cast<const uint32_t*>(bp + 8); } \
        _Pragma("unroll") for (int mi = 0; mi < 4; mi++) \
        _Pragma("unroll") for (int ni = 0; ni < 4; ni++) \
            mma16(c[mi][ni], a[mi], b[ni]); \
    } \
} while (0)

// ---------------------------------------------------------------------------
// merged Q/K projection: z = b*2 + sel; qt gets alpha=1/16
// A=ht (half, M=NSP), B=w (float, N=NC), half out, col bias
// ---------------------------------------------------------------------------
__global__ __launch_bounds__(256, 2)
void qk_gemm(const __half* __restrict__ ht, long sA,
             const float* __restrict__ w0, const float* __restrict__ bias0,
             __half* __restrict__ o0,
             const float* __restrict__ w1, const float* __restrict__ bias1,
             __half* __restrict__ o1)
{
    GEMM_PREAMBLE
    const int b = bz >> 1, sel = bz & 1;
    const float* wsel = sel ? w1 : w0;
    const float* bias = sel ? bias1 : bias0;
    __half* oo = (sel ? o1 : o0) + (long)b * sA;
    const float alpha = sel ? 1.f : 0.0625f;

    const __half* gAh = ht + (long)b * sA + (bm + rr2) * (long)NC + ii2 * 8;
    const float*  gBf = wsel + (bn + rr2) * (long)NC + ii2 * 8;

    const int nIter = NC >> 5;   // 8
    LDG_H(ua, gAh, 0, NC); LDG_F(ub, gBf, 0, NC);
    STS_AB(0);
    __syncthreads();
    for (int it = 0; it < nIter; ++it) {
        const int buf = it & 1;
        if (it + 1 < nIter) { LDG_H(ua, gAh, (it + 1) * 32, NC); LDG_F(ub, gBf, (it + 1) * 32, NC); }
        MMA_BODY16(buf);
        if (it + 1 < nIter) STS_AB(buf ^ 1);
        __syncthreads();
    }

#pragma unroll
    for (int mi = 0; mi < 4; mi++) {
        const long row0 = bm + wm * 64 + mi * 16 + g;
        const long row1 = row0 + 8;
#pragma unroll
        for (int ni = 0; ni < 4; ni++) {
            const long col = bn + wn * 32 + ni * 8 + 2 * t;
            const float bc0 = bias[col], bc1 = bias[col + 1];
            *reinterpret_cast<__half2*>(oo + row0 * NC + col) =
                __floats2half2_rn((c[mi][ni][0] + bc0) * alpha, (c[mi][ni][1] + bc1) * alpha);
            *reinterpret_cast<__half2*>(oo + row1 * NC + col) =
                __floats2half2_rn((c[mi][ni][2] + bc0) * alpha, (c[mi][ni][3] + bc1) * alpha);
        }
    }
}

// ---------------------------------------------------------------------------
// generic GEMM (v projection, out-projection)
// ---------------------------------------------------------------------------
template<int AH, int BH, int BIASCOL, int HASRES, int OUTH>
__global__ __launch_bounds__(256, 2)
void hgemm(const void* Av, long sA, int lda,
           const void* Bv, long sB, int ldb,
           void* Cv, long sC, int ldc,
           int K, float alpha,
           const float* __restrict__ bias,
           const float* __restrict__ resid, long sR)
{
    GEMM_PREAMBLE
    const __half* gAh = AH ? ((const __half*)Av + (long)bz * sA + (bm + rr2) * (long)lda + ii2 * 8) : nullptr;
    const float*  gAf = AH ? nullptr : ((const float*)Av + (long)bz * sA + (bm + rr2) * (long)lda + ii2 * 8);
    const __half* gBh = BH ? ((const __half*)Bv + (long)bz * sB + (bn + rr2) * (long)ldb + ii2 * 8) : nullptr;
    const float*  gBf = BH ? nullptr : ((const float*)Bv + (long)bz * sB + (bn + rr2) * (long)ldb + ii2 * 8);

#define LDG_BOTH(k0) do { \
    if (AH) LDG_H(ua, gAh, k0, lda); else LDG_F(ua, gAf, k0, lda); \
    if (BH) LDG_H(ub, gBh, k0, ldb); else LDG_F(ub, gBf, k0, ldb); \
} while (0)

    const int nIter = K >> 5;
    LDG_BOTH(0);
    STS_AB(0);
    __syncthreads();
    for (int it = 0; it < nIter; ++it) {
        const int buf = it & 1;
        if (it + 1 < nIter) LDG_BOTH((it + 1) * 32);
        MMA_BODY16(buf);
        if (it + 1 < nIter) STS_AB(buf ^ 1);
        __syncthreads();
    }
#undef LDG_BOTH

#pragma unroll
    for (int mi = 0; mi < 4; mi++) {
        const long row0 = bm + wm * 64 + mi * 16 + g;
        const long row1 = row0 + 8;
        float br0 = 0.f, br1 = 0.f;
        if (!BIASCOL && bias) { br0 = bias[row0]; br1 = bias[row1]; }
#pragma unroll
        for (int ni = 0; ni < 4; ni++) {
            const long col = bn + wn * 32 + ni * 8 + 2 * t;
            float2 v0 = make_float2(c[mi][ni][0], c[mi][ni][1]);
            float2 v1 = make_float2(c[mi][ni][2], c[mi][ni][3]);
            if (BIASCOL) {
                const float bc0 = bias[col], bc1 = bias[col + 1];
                v0.x += bc0; v0.y += bc1; v1.x += bc0; v1.y += bc1;
            } else if (bias) {
                v0.x += br0; v0.y += br0; v1.x += br1; v1.y += br1;
            }
            v0.x *= alpha; v0.y *= alpha; v1.x *= alpha; v1.y *= alpha;
            if (OUTH) {
                __half* Cz = (__half*)Cv + (long)bz * sC;
                *reinterpret_cast<__half2*>(Cz + row0 * ldc + col) = __floats2half2_rn(v0.x, v0.y);
                *reinterpret_cast<__half2*>(Cz + row1 * ldc + col) = __floats2half2_rn(v1.x, v1.y);
            } else {
                float* Cz = (float*)Cv + (long)bz * sC;
                if (HASRES) {
                    const float* Rz = resid + (long)bz * sR;
                    float2 r0 = *reinterpret_cast<const float2*>(Rz + row0 * ldc + col);
                    float2 r1 = *reinterpret_cast<const float2*>(Rz + row1 * ldc + col);
                    v0.x += r0.x; v0.y += r0.y; v1.x += r1.x; v1.y += r1.y;
                }
                *reinterpret_cast<float2*>(Cz + row0 * ldc + col) = v0;
                *reinterpret_cast<float2*>(Cz + row1 * ldc + col) = v1;
            }
        }
    }
}

// ---------------------------------------------------------------------------
// logits GEMM: exp(l - m_tile) as half + (m,s) stats
// ---------------------------------------------------------------------------
__global__ __launch_bounds__(256, 2)
void logits_gemm(const __half* __restrict__ A, long sA, int lda,
                 const __half* __restrict__ B, long sB, int ldb,
                 __half* __restrict__ C, long sC, int ldc,
                 float* __restrict__ pm, float* __restrict__ ps)
{
    GEMM_PREAMBLE
    const __half* gAh = A + (long)bz * sA + (bm + rr2) * (long)lda + ii2 * 8;
    const __half* gBh = B + (long)bz * sB + (bn + rr2) * (long)ldb + ii2 * 8;

    const int nIter = NC >> 5;
    LDG_H(ua, gAh, 0, lda); LDG_H(ub, gBh, 0, ldb);
    STS_AB(0);
    __syncthreads();
    for (int it = 0; it < nIter; ++it) {
        const int buf = it & 1;
        if (it + 1 < nIter) { LDG_H(ua, gAh, (it + 1) * 32, lda); LDG_H(ub, gBh, (it + 1) * 32, ldb); }
        MMA_BODY16(buf);
        if (it + 1 < nIter) STS_AB(buf ^ 1);
        __syncthreads();
    }

    float* smf = reinterpret_cast<float*>(smh);
    float* smm = smf;
    float* sms = smf + 512;

#pragma unroll
    for (int mi = 0; mi < 4; mi++)
#pragma unroll
        for (int h = 0; h < 2; h++) {
            float m0 = -1e30f;
#pragma unroll
            for (int ni = 0; ni < 4; ni++)
                m0 = fmaxf(m0, fmaxf(c[mi][ni][2 * h], c[mi][ni][2 * h + 1]));
            m0 = fmaxf(m0, __shfl_xor_sync(0xffffffff, m0, 1));
            m0 = fmaxf(m0, __shfl_xor_sync(0xffffffff, m0, 2));
            if (t == 0) smm[(wm * 64 + mi * 16 + g + 8 * h) * 4 + wn] = m0;
        }
    __syncthreads();

    float mt[4][2];
#pragma unroll
    for (int mi = 0; mi < 4; mi++)
#pragma unroll
        for (int h = 0; h < 2; h++) {
            const int R = wm * 64 + mi * 16 + g + 8 * h;
            float m0 = fmaxf(fmaxf(smm[R * 4 + 0], smm[R * 4 + 1]),
                             fmaxf(smm[R * 4 + 2], smm[R * 4 + 3]));
            mt[mi][h] = m0;
            float s0 = 0.f;
#pragma unroll
            for (int ni = 0; ni < 4; ni++) {
                float e0 = __expf(c[mi][ni][2 * h]     - m0);
                float e1 = __expf(c[mi][ni][2 * h + 1] - m0);
                c[mi][ni][2 * h]     = e0;
                c[mi][ni][2 * h + 1] = e1;
                s0 += e0 + e1;
            }
            s0 += __shfl_xor_sync(0xffffffff, s0, 1);
            s0 += __shfl_xor_sync(0xffffffff, s0, 2);
            if (t == 0) sms[R * 4 + wn] = s0;
        }
    __syncthreads();

    if (wn == 0 && t == 0) {
#pragma unroll
        for (int mi = 0; mi < 4; mi++)
#pragma unroll
            for (int h = 0; h < 2; h++) {
                const int R = wm * 64 + mi * 16 + g + 8 * h;
                const float s0 = sms[R * 4 + 0] + sms[R * 4 + 1]
                               + sms[R * 4 + 2] + sms[R * 4 + 3];
                const long idx = ((long)bz * NSP + bm + R) * NTIL + blockIdx.x;
                pm[idx] = mt[mi][h];
                ps[idx] = s0;
            }
    }

    __half* Cz = C + (long)bz * sC;
#pragma unroll
    for (int mi = 0; mi < 4; mi++) {
        const long row0 = bm + wm * 64 + mi * 16 + g;
        const long row1 = row0 + 8;
#pragma unroll
        for (int ni = 0; ni < 4; ni++) {
            const long col = bn + wn * 32 + ni * 8 + 2 * t;
            *reinterpret_cast<__half2*>(Cz + row0 * ldc + col) =
                __floats2half2_rn(c[mi][ni][0], c[mi][ni][1]);
            *reinterpret_cast<__half2*>(Cz + row1 * ldc + col) =
                __floats2half2_rn(c[mi][ni][2], c[mi][ni][3]);
        }
    }
}

// ---------------------------------------------------------------------------
// combine
// ---------------------------------------------------------------------------
__global__ void combine_kernel(const float* __restrict__ pm,
                               const float* __restrict__ ps,
                               float* __restrict__ sce,
                               float* __restrict__ sci)
{
    const long row = (long)blockIdx.x * 8 + (threadIdx.x >> 5);
    const int lane = threadIdx.x & 31;
    const float m_t = pm[row * NTIL + lane];
    const float s_t = ps[row * NTIL + lane];
    float m = m_t;
#pragma unroll
    for (int off = 16; off > 0; off >>= 1)
        m = fmaxf(m, __shfl_xor_sync(0xffffffff, m, off));
    const float e = __expf(m_t - m);
    float s = s_t * e;
#pragma unroll
    for (int off = 16; off > 0; off >>= 1)
        s += __shfl_xor_sync(0xffffffff, s, off);
    sce[row * NTIL + lane] = e;
    if (lane == 0) sci[row] = 1.f / s;
}

// ---------------------------------------------------------------------------
// PV GEMM split-K: z = b*KSPLIT + slice; each slice does K in [s*1024,(s+1)*1024)
// writes raw fp32 partial to otp[b*KSPLIT + slice]
// ---------------------------------------------------------------------------
__global__ __launch_bounds__(256, 2)
void pv_gemm(const __half* __restrict__ A, long sA, int lda,
             const __half* __restrict__ B, long sB, int ldb,
             float* __restrict__ Cp,
             const float* __restrict__ sce)
{
    GEMM_PREAMBLE
    const int b = bz >> 2, slice = bz & 3;
    const int ko = slice * (NSP / KSPLIT);        // 1024
    const __half* gAh = A + (long)b * sA + (bm + rr2) * (long)lda + ii2 * 8 + ko;
    const __half* gBh = B + (long)b * sB + (bn + rr2) * (long)ldb + ii2 * 8 + ko;
    const float* scb = sce + ((long)b * NSP + bm) * NTIL;
    const int tbase = ko >> 7;

#define LDG_PV(k0) do { \
    LDG_H(ua, gAh, k0, lda); LDG_H(ub, gBh, k0, ldb); \
    const int tm_ = tbase + ((k0) >> 7); \
    __half2 F0 = __float2half2_rn(scb[rr2 * NTIL + tm_]); \
    __half2 F1 = __float2half2_rn(scb[(rr2 + 64) * NTIL + tm_]); \
    __half2* pa0 = reinterpret_cast<__half2*>(&ua[0]); \
    __half2* pa1 = reinterpret_cast<__half2*>(&ua[1]); \
    _Pragma("unroll") for (int q_ = 0; q_ < 4; q_++) { \
        pa0[q_] = __hmul2(pa0[q_], F0); pa1[q_] = __hmul2(pa1[q_], F1); } \
} while (0)

    const int nIter = (NSP / KSPLIT) >> 5;   // 32
    LDG_PV(0);
    STS_AB(0);
    __syncthreads();
    for (int it = 0; it < nIter; ++it) {
        const int buf = it & 1;
        if (it + 1 < nIter) LDG_PV((it + 1) * 32);
        MMA_BODY16(buf);
        if (it + 1 < nIter) STS_AB(buf ^ 1);
        __syncthreads();
    }
#undef LDG_PV

    float* Cz = Cp + (long)bz * ((long)NSP * NC);
#pragma unroll
    for (int mi = 0; mi < 4; mi++) {
        const long row0 = bm + wm * 64 + mi * 16 + g;
        const long row1 = row0 + 8;
#pragma unroll
        for (int ni = 0; ni < 4; ni++) {
            const long col = bn + wn * 32 + ni * 8 + 2 * t;
            *reinterpret_cast<float2*>(Cz + row0 * NC + col) =
                make_float2(c[mi][ni][0], c[mi][ni][1]);
            *reinterpret_cast<float2*>(Cz + row1 * NC + col) =
                make_float2(c[mi][ni][2], c[mi][ni][3]);
        }
    }
}

// ---------------------------------------------------------------------------
// reduce split-K partials, apply 1/s, convert to fp16 ot
// ---------------------------------------------------------------------------
__global__ void pv_reduce(const float* __restrict__ Cp,
                          const float* __restrict__ sci,
                          __half* __restrict__ ot)
{
    const int b = blockIdx.y;
    const long S = (long)NSP * NC;
    const long i = ((long)blockIdx.x * 256 + threadIdx.x) * 4;
    const float* base = Cp + (long)b * KSPLIT * S + i;

    float4 a0 = *reinterpret_cast<const float4*>(base);
    float4 a1 = *reinterpret_cast<const float4*>(base + S);
    float4 a2 = *reinterpret_cast<const float4*>(base + 2 * S);
    float4 a3 = *reinterpret_cast<const float4*>(base + 3 * S);
    const float iv = sci[(long)b * NSP + (i >> 8)];   // i / NC

    float4 r;
    r.x = (a0.x + a1.x + a2.x + a3.x) * iv;
    r.y = (a0.y + a1.y + a2.y + a3.y) * iv;
    r.z = (a0.z + a1.z + a2.z + a3.z) * iv;
    r.w = (a0.w + a1.w + a2.w + a3.w) * iv;

    __half2* o = reinterpret_cast<__half2*>(ot + (long)b * S + i);
    o[0] = __floats2half2_rn(r.x, r.y);
    o[1] = __floats2half2_rn(r.z, r.w);
}

// ---------------------------------------------------------------------------
extern "C" void kernel_launch(void* const* d_in, const int* in_sizes, int n_in,
                              void* d_out, int out_size)
{
    const float* x   = (const float*)d_in[0];
    const float* gnw = (const float*)d_in[1];
    const float* gnb = (const float*)d_in[2];
    const float* wq  = (const float*)d_in[3];
    const float* bq  = (const float*)d_in[4];
    const float* wk  = (const float*)d_in[5];
    const float* bk  = (const float*)d_in[6];
    const float* wv  = (const float*)d_in[7];
    const float* bv  = (const float*)d_in[8];
    const float* wp  = (const float*)d_in[9];
    const float* bp  = (const float*)d_in[10];
    float* out = (float*)d_out;

    __half *ht, *qt, *kt, *v, *ot, *attn;
    float *otp, *stat, *pm, *ps, *sce, *sci;
    cudaGetSymbolAddress((void**)&ht,   g_ht);
    cudaGetSymbolAddress((void**)&qt,   g_qt);
    cudaGetSymbolAddress((void**)&kt,   g_kt);
    cudaGetSymbolAddress((void**)&v,    g_v);
    cudaGetSymbolAddress((void**)&ot,   g_ot);
    cudaGetSymbolAddress((void**)&attn, g_attn);
    cudaGetSymbolAddress((void**)&otp,  g_otp);
    cudaGetSymbolAddress((void**)&stat, g_stat);
    cudaGetSymbolAddress((void**)&pm,   g_pm);
    cudaGetSymbolAddress((void**)&ps,   g_ps);
    cudaGetSymbolAddress((void**)&sce,  g_sce);
    cudaGetSymbolAddress((void**)&sci,  g_sci);

    const long sCN = (long)NC * NSP;
    const long sNN = (long)NSP * NSP;
    const int SMEM = 4 * TSZH * 2;   // 40960 bytes

    // 1) GroupNorm
    gn_stats<<<NB * NGRP, 256>>>(x, stat);
    gn_apply<<<dim3(NC / 32, NSP / 32, NB), dim3(32, 8)>>>(x, gnw, gnb, stat, ht);

    // 2) Q+K merged (256 CTAs), V projection
    dim3 gQK(NC / 128, NSP / 128, NB * 2);
    qk_gemm<<<gQK, 256, SMEM>>>(ht, sCN, wq, bq, qt, wk, bk, kt);
    dim3 gV(NSP / 128, NC / 128, NB);
    hgemm<0, 1, 0, 0, 1><<<gV, 256, SMEM>>>(wv, 0, NC, ht, sCN, NC, v, sCN, NSP,
                                            NC, 1.f, bv, nullptr, 0);

    // 3) logits with fused exp + tile stats
    dim3 gS(NSP / 128, NSP / 128, NB);
    logits_gemm<<<gS, 256, SMEM>>>(qt, sCN, NC, kt, sCN, NC, attn, sNN, NSP,
                                   pm, ps);

    // 4) combine
    combine_kernel<<<NB * NSP / 8, 256>>>(pm, ps, sce, sci);

    // 5) PV split-K (512 CTAs) + reduce
    dim3 gO(NC / 128, NSP / 128, NB * KSPLIT);
    pv_gemm<<<gO, 256, SMEM>>>(attn, sNN, NSP, v, sCN, NSP, otp, sce);
    pv_reduce<<<dim3((unsigned)(sCN / 1024), NB), 256>>>(otp, sci, ot);

    // 6) out-projection + residual
    hgemm<0, 1, 0, 1, 0><<<gV, 256, SMEM>>>(wp, 0, NC, ot, sCN, NC, out, sCN, NSP,
                                            NC, 1.f, bp, x, sCN);
}

// round 11
// speedup vs baseline: 1.9741x; 1.0947x over previous
#include <cuda_runtime.h>
#include <cuda_fp16.h>
#include <cstdint>

#define NB   2
#define NC   256
#define NSP  4096
#define NGRP 32
#define CPG  8
#define NTIL 32
#define KSPLIT 4
#define STAGES 4

// ---------------- scratch (no allocation allowed) ----------------
__device__ __half g_ht  [(size_t)NB * NC * NSP];
__device__ __half g_qt  [(size_t)NB * NC * NSP];
__device__ __half g_kt  [(size_t)NB * NC * NSP];
__device__ __half g_v   [(size_t)NB * NC * NSP];
__device__ __half g_ot  [(size_t)NB * NC * NSP];
__device__ __half g_attn[(size_t)NB * NSP * NSP];          // 64 MiB
__device__ float  g_otp [(size_t)NB * KSPLIT * NC * NSP];  // fp32 partials
__device__ __half g_wh  [4 * NC * NC];                     // fp16 weights q,k,v,p
__device__ float  g_stat[NB * NGRP * 2];
__device__ float  g_pm  [(size_t)NB * NSP * NTIL];
__device__ float  g_ps  [(size_t)NB * NSP * NTIL];
__device__ float  g_sce [(size_t)NB * NSP * NTIL];
__device__ float  g_sci [(size_t)NB * NSP];

// ---------------- helpers ----------------
__device__ __forceinline__ uint32_t smem_u32(const void* p) {
    uint32_t r;
    asm("{ .reg .u64 t; cvta.to.shared.u64 t, %1; cvt.u32.u64 %0, t; }"
        : "=r"(r) : "l"(p));
    return r;
}
__device__ __forceinline__ void mma16(float* c, const uint32_t* a, const uint32_t* b) {
    asm volatile(
        "mma.sync.aligned.m16n8k16.row.col.f32.f16.f16.f32 "
        "{%0,%1,%2,%3}, {%4,%5,%6,%7}, {%8,%9}, {%0,%1,%2,%3};\n"
        : "+f"(c[0]), "+f"(c[1]), "+f"(c[2]), "+f"(c[3])
        : "r"(a[0]), "r"(a[1]), "r"(a[2]), "r"(a[3]),
          "r"(b[0]), "r"(b[1]));
}
__device__ __forceinline__ uint32_t hmul2u(uint32_t a, uint32_t f) {
    __half2 r = __hmul2(*reinterpret_cast<__half2*>(&a),
                        *reinterpret_cast<__half2*>(&f));
    return *reinterpret_cast<uint32_t*>(&r);
}
__device__ __forceinline__ uint32_t h2u(__half2 h) {
    return *reinterpret_cast<uint32_t*>(&h);
}

// ---------------- weight fp32 -> fp16 ----------------
__global__ void wconv(const float* __restrict__ wq, const float* __restrict__ wk,
                      const float* __restrict__ wv, const float* __restrict__ wp,
                      __half* __restrict__ wh)
{
    const int z = blockIdx.y;
    const float* w = z == 0 ? wq : z == 1 ? wk : z == 2 ? wv : wp;
    const int i = (blockIdx.x * 256 + threadIdx.x) * 4;
    float4 v = *reinterpret_cast<const float4*>(w + i);
    __half2* o = reinterpret_cast<__half2*>(wh + z * NC * NC + i);
    o[0] = __floats2half2_rn(v.x, v.y);
    o[1] = __floats2half2_rn(v.z, v.w);
}

// ---------------- GroupNorm stats ----------------
__global__ void gn_stats(const float* __restrict__ x, float* __restrict__ stat)
{
    const int b = blockIdx.x >> 5;
    const int g = blockIdx.x & 31;
    const float* xp = x + ((long)b * NC + (long)g * CPG) * NSP;
    const int tid = threadIdx.x;
    const int TOT = CPG * NSP;

    float s = 0.f, ss = 0.f;
    for (int i = tid * 4; i < TOT; i += 1024) {
        float4 v = *reinterpret_cast<const float4*>(xp + i);
        s  += v.x + v.y + v.z + v.w;
        ss += v.x * v.x + v.y * v.y + v.z * v.z + v.w * v.w;
    }
    __shared__ float rs[256], rss[256];
    rs[tid] = s; rss[tid] = ss;
    __syncthreads();
    for (int off = 128; off > 0; off >>= 1) {
        if (tid < off) { rs[tid] += rs[tid + off]; rss[tid] += rss[tid + off]; }
        __syncthreads();
    }
    if (tid == 0) {
        float mean = rs[0] / (float)TOT;
        float var  = rss[0] / (float)TOT - mean * mean;
        stat[blockIdx.x * 2 + 0] = mean;
        stat[blockIdx.x * 2 + 1] = rsqrtf(var + 1e-5f);
    }
}

// ---------------- GroupNorm apply + transpose -> fp16 ht ----------------
__global__ void gn_apply(const float* __restrict__ x,
                         const float* __restrict__ w,
                         const float* __restrict__ bb,
                         const float* __restrict__ stat,
                         __half* __restrict__ ht)
{
    __shared__ float t[32][33];
    const int b  = blockIdx.z;
    const int c0 = blockIdx.x * 32;
    const int n0 = blockIdx.y * 32;
    const int tx = threadIdx.x, ty = threadIdx.y;
    const float* xb = x  + (long)b * NC * NSP;
    __half*      hb = ht + (long)b * NSP * NC;

#pragma unroll
    for (int j = 0; j < 4; j++) {
        const int c = c0 + ty + j * 8;
        const int g = c >> 3;
        const float mean = stat[(b * NGRP + g) * 2 + 0];
        const float inv  = stat[(b * NGRP + g) * 2 + 1];
        const float wc = w[c] * inv;
        const float bc = bb[c] - mean * wc;
        t[ty + j * 8][tx] = xb[(long)c * NSP + n0 + tx] * wc + bc;
    }
    __syncthreads();
#pragma unroll
    for (int j = 0; j < 4; j++) {
        const int n = n0 + ty + j * 8;
        hb[(long)n * NC + c0 + tx] = __float2half_rn(t[tx][ty + j * 8]);
    }
}

// =============== fp16 GEMM, cp.async 4-stage pipeline ===============
#define TSZH 5120
#define SMEMB (2 * STAGES * TSZH * 2)   // 81920 bytes

#define GEMM_PREAMBLE \
    extern __shared__ __half smh[]; \
    const uint32_t sb = smem_u32(smh); \
    const int tid = threadIdx.x; \
    const int wid = tid >> 5, lane = tid & 31; \
    const int wm = wid >> 2, wn = wid & 3; \
    const int g = lane >> 2, t = lane & 3; \
    const int bz = blockIdx.z; \
    const long bm = (long)blockIdx.y * 128; \
    const long bn = (long)blockIdx.x * 128; \
    const int rr2 = tid >> 2, ii2 = tid & 3; \
    float c[4][4][4]; \
    _Pragma("unroll") for (int mi = 0; mi < 4; mi++) \
    _Pragma("unroll") for (int ni = 0; ni < 4; ni++) \
    _Pragma("unroll") for (int j = 0; j < 4; j++) c[mi][ni][j] = 0.f;

#define CPA_ISSUE(buf, k0) do { \
    uint32_t da_ = sb + (uint32_t)(((buf) * TSZH + rr2 * 40 + ii2 * 8) * 2); \
    asm volatile("cp.async.cg.shared.global [%0], [%1], 16;" \
                 :: "r"(da_), "l"(gAh + (long)(k0)) : "memory"); \
    asm volatile("cp.async.cg.shared.global [%0], [%1], 16;" \
                 :: "r"(da_ + 64 * 40 * 2), "l"(gAh + (long)(k0) + 64L * lda) : "memory"); \
    uint32_t db_ = sb + (uint32_t)(((STAGES + (buf)) * TSZH + rr2 * 40 + ii2 * 8) * 2); \
    asm volatile("cp.async.cg.shared.global [%0], [%1], 16;" \
                 :: "r"(db_), "l"(gBh + (long)(k0)) : "memory"); \
    asm volatile("cp.async.cg.shared.global [%0], [%1], 16;" \
                 :: "r"(db_ + 64 * 40 * 2), "l"(gBh + (long)(k0) + 64L * ldb) : "memory"); \
} while (0)

#define CPA_COMMIT() asm volatile("cp.async.commit_group;" ::: "memory")
#define CPA_WAIT()   asm volatile("cp.async.wait_group %0;" :: "n"(STAGES - 2) : "memory")

#define LOAD_FRAGS(buf) \
    uint32_t a[4][4], b[4][2]; \
    { const __half* As = smh + (buf) * TSZH + (wm * 64 + g) * 40 + 2 * t + kk; \
      const __half* Bs = smh + (STAGES + (buf)) * TSZH + (wn * 32 + g) * 40 + 2 * t + kk; \
      _Pragma("unroll") for (int mi = 0; mi < 4; mi++) { \
          const __half* ap = As + mi * 16 * 40; \
          a[mi][0] = *reinterpret_cast<const uint32_t*>(ap); \
          a[mi][1] = *reinterpret_cast<const uint32_t*>(ap + 8 * 40); \
          a[mi][2] = *reinterpret_cast<const uint32_t*>(ap + 8); \
          a[mi][3] = *reinterpret_cast<const uint32_t*>(ap + 8 * 40 + 8); } \
      _Pragma("unroll") for (int ni = 0; ni < 4; ni++) { \
          const __half* bp = Bs + ni * 8 * 40; \
          b[ni][0] = *reinterpret_cast<const uint32_t*>(bp); \
          b[ni][1] = *reinterpret_cast<const uint32_t*>(bp + 8); } }

#define MMA_BODY16(buf) do { \
    _Pragma("unroll") for (int kk = 0; kk < 32; kk += 16) { \
        LOAD_FRAGS(buf) \
        _Pragma("unroll") for (int mi = 0; mi < 4; mi++) \
        _Pragma("unroll") for (int ni = 0; ni < 4; ni++) \
            mma16(c[mi][ni], a[mi], b[ni]); \
    } \
} while (0)

// scaled variant (PV): multiply A fragments by per-row half2 factors
#define MMA_BODY16S(buf) do { \
    _Pragma("unroll") for (int kk = 0; kk < 32; kk += 16) { \
        LOAD_FRAGS(buf) \
        _Pragma("unroll") for (int mi = 0; mi < 4; mi++) { \
            a[mi][0] = hmul2u(a[mi][0], F0[mi]); \
            a[mi][2] = hmul2u(a[mi][2], F0[mi]); \
            a[mi][1] = hmul2u(a[mi][1], F1[mi]); \
            a[mi][3] = hmul2u(a[mi][3], F1[mi]); } \
        _Pragma("unroll") for (int mi = 0; mi < 4; mi++) \
        _Pragma("unroll") for (int ni = 0; ni < 4; ni++) \
            mma16(c[mi][ni], a[mi], b[ni]); \
    } \
} while (0)

#define PIPE_LOOP(NITER, BODY) do { \
    int kload = 0; \
    _Pragma("unroll") for (int s = 0; s < STAGES - 1; s++) { \
        if (s < (NITER)) CPA_ISSUE(s, kload); \
        CPA_COMMIT(); kload += 32; } \
    for (int it = 0; it < (NITER); ++it) { \
        CPA_WAIT(); \
        __syncthreads(); \
        if (it + STAGES - 1 < (NITER)) CPA_ISSUE((it + STAGES - 1) % STAGES, kload); \
        CPA_COMMIT(); kload += 32; \
        BODY; \
    } \
} while (0)

// ---------------------------------------------------------------------------
// merged Q/K projection: z = b*2 + sel
// ---------------------------------------------------------------------------
__global__ __launch_bounds__(256, 2)
void qk_gemm(const __half* __restrict__ ht, long sA,
             const __half* __restrict__ wh,
             const float* __restrict__ bias0, __half* __restrict__ o0,
             const float* __restrict__ bias1, __half* __restrict__ o1)
{
    GEMM_PREAMBLE
    const int b = bz >> 1, sel = bz & 1;
    const float* bias = sel ? bias1 : bias0;
    __half* oo = (sel ? o1 : o0) + (long)b * sA;
    const float alpha = sel ? 1.f : 0.0625f;
    const int lda = NC, ldb = NC;

    const __half* gAh = ht + (long)b * sA + (bm + rr2) * (long)NC + ii2 * 8;
    const __half* gBh = wh + (long)sel * NC * NC + (bn + rr2) * (long)NC + ii2 * 8;

    PIPE_LOOP(NC >> 5, MMA_BODY16(it % STAGES));

#pragma unroll
    for (int mi = 0; mi < 4; mi++) {
        const long row0 = bm + wm * 64 + mi * 16 + g;
        const long row1 = row0 + 8;
#pragma unroll
        for (int ni = 0; ni < 4; ni++) {
            const long col = bn + wn * 32 + ni * 8 + 2 * t;
            const float bc0 = bias[col], bc1 = bias[col + 1];
            *reinterpret_cast<__half2*>(oo + row0 * NC + col) =
                __floats2half2_rn((c[mi][ni][0] + bc0) * alpha, (c[mi][ni][1] + bc1) * alpha);
            *reinterpret_cast<__half2*>(oo + row1 * NC + col) =
                __floats2half2_rn((c[mi][ni][2] + bc0) * alpha, (c[mi][ni][3] + bc1) * alpha);
        }
    }
}

// ---------------------------------------------------------------------------
// generic fp16 GEMM (v projection OUTH=1; out-projection OUTH=0 + resid)
// bias indexed by row.
// ---------------------------------------------------------------------------
template<int HASRES, int OUTH>
__global__ __launch_bounds__(256, 2)
void hgemm(const __half* __restrict__ A, long sA, int lda,
           const __half* __restrict__ B, long sB, int ldb,
           void* Cv, long sC, int ldc, int K,
           const float* __restrict__ bias,
           const float* __restrict__ resid, long sR)
{
    GEMM_PREAMBLE
    const __half* gAh = A + (long)bz * sA + (bm + rr2) * (long)lda + ii2 * 8;
    const __half* gBh = B + (long)bz * sB + (bn + rr2) * (long)ldb + ii2 * 8;

    PIPE_LOOP(K >> 5, MMA_BODY16(it % STAGES));

#pragma unroll
    for (int mi = 0; mi < 4; mi++) {
        const long row0 = bm + wm * 64 + mi * 16 + g;
        const long row1 = row0 + 8;
        const float br0 = bias ? bias[row0] : 0.f;
        const float br1 = bias ? bias[row1] : 0.f;
#pragma unroll
        for (int ni = 0; ni < 4; ni++) {
            const long col = bn + wn * 32 + ni * 8 + 2 * t;
            float2 v0 = make_float2(c[mi][ni][0] + br0, c[mi][ni][1] + br0);
            float2 v1 = make_float2(c[mi][ni][2] + br1, c[mi][ni][3] + br1);
            if (OUTH) {
                __half* Cz = (__half*)Cv + (long)bz * sC;
                *reinterpret_cast<__half2*>(Cz + row0 * ldc + col) = __floats2half2_rn(v0.x, v0.y);
                *reinterpret_cast<__half2*>(Cz + row1 * ldc + col) = __floats2half2_rn(v1.x, v1.y);
            } else {
                float* Cz = (float*)Cv + (long)bz * sC;
                if (HASRES) {
                    const float* Rz = resid + (long)bz * sR;
                    float2 r0 = *reinterpret_cast<const float2*>(Rz + row0 * ldc + col);
                    float2 r1 = *reinterpret_cast<const float2*>(Rz + row1 * ldc + col);
                    v0.x += r0.x; v0.y += r0.y; v1.x += r1.x; v1.y += r1.y;
                }
                *reinterpret_cast<float2*>(Cz + row0 * ldc + col) = v0;
                *reinterpret_cast<float2*>(Cz + row1 * ldc + col) = v1;
            }
        }
    }
}

// ---------------------------------------------------------------------------
// logits GEMM: exp(l - m_tile) as half + (m,s) stats
// ---------------------------------------------------------------------------
__global__ __launch_bounds__(256, 2)
void logits_gemm(const __half* __restrict__ A, long sA, int lda,
                 const __half* __restrict__ B, long sB, int ldb,
                 __half* __restrict__ C, long sC, int ldc,
                 float* __restrict__ pm, float* __restrict__ ps)
{
    GEMM_PREAMBLE
    const __half* gAh = A + (long)bz * sA + (bm + rr2) * (long)lda + ii2 * 8;
    const __half* gBh = B + (long)bz * sB + (bn + rr2) * (long)ldb + ii2 * 8;

    PIPE_LOOP(NC >> 5, MMA_BODY16(it % STAGES));
    __syncthreads();   // smem reuse for reductions

    float* smf = reinterpret_cast<float*>(smh);
    float* smm = smf;
    float* sms = smf + 512;

#pragma unroll
    for (int mi = 0; mi < 4; mi++)
#pragma unroll
        for (int h = 0; h < 2; h++) {
            float m0 = -1e30f;
#pragma unroll
            for (int ni = 0; ni < 4; ni++)
                m0 = fmaxf(m0, fmaxf(c[mi][ni][2 * h], c[mi][ni][2 * h + 1]));
            m0 = fmaxf(m0, __shfl_xor_sync(0xffffffff, m0, 1));
            m0 = fmaxf(m0, __shfl_xor_sync(0xffffffff, m0, 2));
            if (t == 0) smm[(wm * 64 + mi * 16 + g + 8 * h) * 4 + wn] = m0;
        }
    __syncthreads();

    float mt[4][2];
#pragma unroll
    for (int mi = 0; mi < 4; mi++)
#pragma unroll
        for (int h = 0; h < 2; h++) {
            const int R = wm * 64 + mi * 16 + g + 8 * h;
            float m0 = fmaxf(fmaxf(smm[R * 4 + 0], smm[R * 4 + 1]),
                             fmaxf(smm[R * 4 + 2], smm[R * 4 + 3]));
            mt[mi][h] = m0;
            float s0 = 0.f;
#pragma unroll
            for (int ni = 0; ni < 4; ni++) {
                float e0 = __expf(c[mi][ni][2 * h]     - m0);
                float e1 = __expf(c[mi][ni][2 * h + 1] - m0);
                c[mi][ni][2 * h]     = e0;
                c[mi][ni][2 * h + 1] = e1;
                s0 += e0 + e1;
            }
            s0 += __shfl_xor_sync(0xffffffff, s0, 1);
            s0 += __shfl_xor_sync(0xffffffff, s0, 2);
            if (t == 0) sms[R * 4 + wn] = s0;
        }
    __syncthreads();

    if (wn == 0 && t == 0) {
#pragma unroll
        for (int mi = 0; mi < 4; mi++)
#pragma unroll
            for (int h = 0; h < 2; h++) {
                const int R = wm * 64 + mi * 16 + g + 8 * h;
                const float s0 = sms[R * 4 + 0] + sms[R * 4 + 1]
                               + sms[R * 4 + 2] + sms[R * 4 + 3];
                const long idx = ((long)bz * NSP + bm + R) * NTIL + blockIdx.x;
                pm[idx] = mt[mi][h];
                ps[idx] = s0;
            }
    }

    __half* Cz = C + (long)bz * sC;
#pragma unroll
    for (int mi = 0; mi < 4; mi++) {
        const long row0 = bm + wm * 64 + mi * 16 + g;
        const long row1 = row0 + 8;
#pragma unroll
        for (int ni = 0; ni < 4; ni++) {
            const long col = bn + wn * 32 + ni * 8 + 2 * t;
            *reinterpret_cast<__half2*>(Cz + row0 * ldc + col) =
                __floats2half2_rn(c[mi][ni][0], c[mi][ni][1]);
            *reinterpret_cast<__half2*>(Cz + row1 * ldc + col) =
                __floats2half2_rn(c[mi][ni][2], c[mi][ni][3]);
        }
    }
}

// ---------------------------------------------------------------------------
// combine
// ---------------------------------------------------------------------------
__global__ void combine_kernel(const float* __restrict__ pm,
                               const float* __restrict__ ps,
                               float* __restrict__ sce,
                               float* __restrict__ sci)
{
    const long row = (long)blockIdx.x * 8 + (threadIdx.x >> 5);
    const int lane = threadIdx.x & 31;
    const float m_t = pm[row * NTIL + lane];
    const float s_t = ps[row * NTIL + lane];
    float m = m_t;
#pragma unroll
    for (int off = 16; off > 0; off >>= 1)
        m = fmaxf(m, __shfl_xor_sync(0xffffffff, m, off));
    const float e = __expf(m_t - m);
    float s = s_t * e;
#pragma unroll
    for (int off = 16; off > 0; off >>= 1)
        s += __shfl_xor_sync(0xffffffff, s, off);
    sce[row * NTIL + lane] = e;
    if (lane == 0) sci[row] = 1.f / s;
}

// ---------------------------------------------------------------------------
// PV GEMM split-K with fragment-level e_t scaling
// ---------------------------------------------------------------------------
__global__ __launch_bounds__(256, 2)
void pv_gemm(const __half* __restrict__ A, long sA, int lda,
             const __half* __restrict__ B, long sB, int ldb,
             float* __restrict__ Cp,
             const float* __restrict__ sce)
{
    GEMM_PREAMBLE
    const int b = bz >> 2, slice = bz & 3;
    const int ko = slice * (NSP / KSPLIT);
    const __half* gAh = A + (long)b * sA + (bm + rr2) * (long)lda + ii2 * 8 + ko;
    const __half* gBh = B + (long)b * sB + (bn + rr2) * (long)ldb + ii2 * 8 + ko;
    const float* scb = sce + ((long)b * NSP + bm) * NTIL;
    const int tbase = ko >> 7;

    uint32_t F0[4], F1[4];

    PIPE_LOOP((NSP / KSPLIT) >> 5,
        if ((it & 3) == 0) {
            const int tm = tbase + (it >> 2);
#pragma unroll
            for (int mi = 0; mi < 4; mi++) {
                const int r0 = wm * 64 + mi * 16 + g;
                F0[mi] = h2u(__float2half2_rn(scb[r0 * NTIL + tm]));
                F1[mi] = h2u(__float2half2_rn(scb[(r0 + 8) * NTIL + tm]));
            }
        }
        MMA_BODY16S(it % STAGES)
    );

    float* Cz = Cp + (long)bz * ((long)NSP * NC);
#pragma unroll
    for (int mi = 0; mi < 4; mi++) {
        const long row0 = bm + wm * 64 + mi * 16 + g;
        const long row1 = row0 + 8;
#pragma unroll
        for (int ni = 0; ni < 4; ni++) {
            const long col = bn + wn * 32 + ni * 8 + 2 * t;
            *reinterpret_cast<float2*>(Cz + row0 * NC + col) =
                make_float2(c[mi][ni][0], c[mi][ni][1]);
            *reinterpret_cast<float2*>(Cz + row1 * NC + col) =
                make_float2(c[mi][ni][2], c[mi][ni][3]);
        }
    }
}

// ---------------------------------------------------------------------------
// reduce split-K partials, apply 1/s, convert to fp16 ot
// ---------------------------------------------------------------------------
__global__ void pv_reduce(const float* __restrict__ Cp,
                          const float* __restrict__ sci,
                          __half* __restrict__ ot)
{
    const int b = blockIdx.y;
    const long S = (long)NSP * NC;
    const long i = ((long)blockIdx.x * 256 + threadIdx.x) * 4;
    const float* base = Cp + (long)b * KSPLIT * S + i;

    float4 a0 = *reinterpret_cast<const float4*>(base);
    float4 a1 = *reinterpret_cast<const float4*>(base + S);
    float4 a2 = *reinterpret_cast<const float4*>(base + 2 * S);
    float4 a3 = *reinterpret_cast<const float4*>(base + 3 * S);
    const float iv = sci[(long)b * NSP + (i >> 8)];

    float4 r;
    r.x = (a0.x + a1.x + a2.x + a3.x) * iv;
    r.y = (a0.y + a1.y + a2.y + a3.y) * iv;
    r.z = (a0.z + a1.z + a2.z + a3.z) * iv;
    r.w = (a0.w + a1.w + a2.w + a3.w) * iv;

    __half2* o = reinterpret_cast<__half2*>(ot + (long)b * S + i);
    o[0] = __floats2half2_rn(r.x, r.y);
    o[1] = __floats2half2_rn(r.z, r.w);
}

// ---------------------------------------------------------------------------
extern "C" void kernel_launch(void* const* d_in, const int* in_sizes, int n_in,
                              void* d_out, int out_size)
{
    const float* x   = (const float*)d_in[0];
    const float* gnw = (const float*)d_in[1];
    const float* gnb = (const float*)d_in[2];
    const float* wq  = (const float*)d_in[3];
    const float* bq  = (const float*)d_in[4];
    const float* wk  = (const float*)d_in[5];
    const float* bk  = (const float*)d_in[6];
    const float* wv  = (const float*)d_in[7];
    const float* bv  = (const float*)d_in[8];
    const float* wp  = (const float*)d_in[9];
    const float* bp  = (const float*)d_in[10];
    float* out = (float*)d_out;

    __half *ht, *qt, *kt, *v, *ot, *attn, *wh;
    float *otp, *stat, *pm, *ps, *sce, *sci;
    cudaGetSymbolAddress((void**)&ht,   g_ht);
    cudaGetSymbolAddress((void**)&qt,   g_qt);
    cudaGetSymbolAddress((void**)&kt,   g_kt);
    cudaGetSymbolAddress((void**)&v,    g_v);
    cudaGetSymbolAddress((void**)&ot,   g_ot);
    cudaGetSymbolAddress((void**)&attn, g_attn);
    cudaGetSymbolAddress((void**)&wh,   g_wh);
    cudaGetSymbolAddress((void**)&otp,  g_otp);
    cudaGetSymbolAddress((void**)&stat, g_stat);
    cudaGetSymbolAddress((void**)&pm,   g_pm);
    cudaGetSymbolAddress((void**)&ps,   g_ps);
    cudaGetSymbolAddress((void**)&sce,  g_sce);
    cudaGetSymbolAddress((void**)&sci,  g_sci);

    const long sCN = (long)NC * NSP;
    const long sNN = (long)NSP * NSP;

    cudaFuncSetAttribute(qk_gemm,     cudaFuncAttributeMaxDynamicSharedMemorySize, SMEMB);
    cudaFuncSetAttribute(hgemm<0, 1>, cudaFuncAttributeMaxDynamicSharedMemorySize, SMEMB);
    cudaFuncSetAttribute(hgemm<1, 0>, cudaFuncAttributeMaxDynamicSharedMemorySize, SMEMB);
    cudaFuncSetAttribute(logits_gemm, cudaFuncAttributeMaxDynamicSharedMemorySize, SMEMB);
    cudaFuncSetAttribute(pv_gemm,     cudaFuncAttributeMaxDynamicSharedMemorySize, SMEMB);

    // 0) weights -> fp16
    wconv<<<dim3(NC * NC / 1024, 4), 256>>>(wq, wk, wv, wp, wh);

    // 1) GroupNorm
    gn_stats<<<NB * NGRP, 256>>>(x, stat);
    gn_apply<<<dim3(NC / 32, NSP / 32, NB), dim3(32, 8)>>>(x, gnw, gnb, stat, ht);

    // 2) Q+K merged, V projection
    dim3 gQK(NC / 128, NSP / 128, NB * 2);
    qk_gemm<<<gQK, 256, SMEMB>>>(ht, sCN, wh, bq, qt, bk, kt);
    dim3 gV(NSP / 128, NC / 128, NB);
    hgemm<0, 1><<<gV, 256, SMEMB>>>(wh + 2L * NC * NC, 0, NC, ht, sCN, NC,
                                    v, sCN, NSP, NC, bv, nullptr, 0);

    // 3) logits with fused exp + tile stats
    dim3 gS(NSP / 128, NSP / 128, NB);
    logits_gemm<<<gS, 256, SMEMB>>>(qt, sCN, NC, kt, sCN, NC, attn, sNN, NSP,
                                    pm, ps);

    // 4) combine
    combine_kernel<<<NB * NSP / 8, 256>>>(pm, ps, sce, sci);

    // 5) PV split-K + reduce
    dim3 gO(NC / 128, NSP / 128, NB * KSPLIT);
    pv_gemm<<<gO, 256, SMEMB>>>(attn, sNN, NSP, v, sCN, NSP, otp, sce);
    pv_reduce<<<dim3((unsigned)(sCN / 1024), NB), 256>>>(otp, sci, ot);

    // 6) out-projection + residual
    hgemm<1, 0><<<gV, 256, SMEMB>>>(wh + 3L * NC * NC, 0, NC, ot, sCN, NC,
                                    out, sCN, NSP, NC, bp, x, sCN);
}

// round 12
// speedup vs baseline: 2.0157x; 1.0210x over previous
#include <cuda_runtime.h>
#include <cuda_fp16.h>
#include <cstdint>

#define NB   2
#define NC   256
#define NSP  4096
#define NGRP 32
#define CPG  8
#define NTIL 32
#define KSPLIT 2
#define STAGES 4

// ---------------- scratch (no allocation allowed) ----------------
__device__ __half g_ht  [(size_t)NB * NC * NSP];
__device__ __half g_qt  [(size_t)NB * NC * NSP];
__device__ __half g_kt  [(size_t)NB * NC * NSP];
__device__ __half g_v   [(size_t)NB * NC * NSP];
__device__ __half g_ot  [(size_t)NB * NC * NSP];
__device__ __half g_attn[(size_t)NB * NSP * NSP];          // 64 MiB
__device__ float  g_otp [(size_t)NB * KSPLIT * NC * NSP];  // fp32 partials
__device__ __half g_wh  [4 * NC * NC];                     // fp16 weights q,k,v,p
__device__ float  g_stat[NB * NGRP * 2];
__device__ float  g_pm  [(size_t)NB * NSP * NTIL];
__device__ float  g_ps  [(size_t)NB * NSP * NTIL];
__device__ float  g_sce [(size_t)NB * NSP * NTIL];
__device__ float  g_sci [(size_t)NB * NSP];

// ---------------- helpers ----------------
__device__ __forceinline__ uint32_t smem_u32(const void* p) {
    uint32_t r;
    asm("{ .reg .u64 t; cvta.to.shared.u64 t, %1; cvt.u32.u64 %0, t; }"
        : "=r"(r) : "l"(p));
    return r;
}
__device__ __forceinline__ void mma16(float* c, const uint32_t* a, const uint32_t* b) {
    asm volatile(
        "mma.sync.aligned.m16n8k16.row.col.f32.f16.f16.f32 "
        "{%0,%1,%2,%3}, {%4,%5,%6,%7}, {%8,%9}, {%0,%1,%2,%3};\n"
        : "+f"(c[0]), "+f"(c[1]), "+f"(c[2]), "+f"(c[3])
        : "r"(a[0]), "r"(a[1]), "r"(a[2]), "r"(a[3]),
          "r"(b[0]), "r"(b[1]));
}
__device__ __forceinline__ uint32_t hmul2u(uint32_t a, uint32_t f) {
    __half2 r = __hmul2(*reinterpret_cast<__half2*>(&a),
                        *reinterpret_cast<__half2*>(&f));
    return *reinterpret_cast<uint32_t*>(&r);
}
__device__ __forceinline__ uint32_t h2u(__half2 h) {
    return *reinterpret_cast<uint32_t*>(&h);
}

// ---------------- weight fp32 -> fp16 ----------------
__global__ void wconv(const float* __restrict__ wq, const float* __restrict__ wk,
                      const float* __restrict__ wv, const float* __restrict__ wp,
                      __half* __restrict__ wh)
{
    const int z = blockIdx.y;
    const float* w = z == 0 ? wq : z == 1 ? wk : z == 2 ? wv : wp;
    const int i = (blockIdx.x * 256 + threadIdx.x) * 4;
    float4 v = *reinterpret_cast<const float4*>(w + i);
    __half2* o = reinterpret_cast<__half2*>(wh + z * NC * NC + i);
    o[0] = __floats2half2_rn(v.x, v.y);
    o[1] = __floats2half2_rn(v.z, v.w);
}

// ---------------- GroupNorm stats ----------------
__global__ void gn_stats(const float* __restrict__ x, float* __restrict__ stat)
{
    const int b = blockIdx.x >> 5;
    const int g = blockIdx.x & 31;
    const float* xp = x + ((long)b * NC + (long)g * CPG) * NSP;
    const int tid = threadIdx.x;
    const int TOT = CPG * NSP;

    float s = 0.f, ss = 0.f;
    for (int i = tid * 4; i < TOT; i += 1024) {
        float4 v = *reinterpret_cast<const float4*>(xp + i);
        s  += v.x + v.y + v.z + v.w;
        ss += v.x * v.x + v.y * v.y + v.z * v.z + v.w * v.w;
    }
    __shared__ float rs[256], rss[256];
    rs[tid] = s; rss[tid] = ss;
    __syncthreads();
    for (int off = 128; off > 0; off >>= 1) {
        if (tid < off) { rs[tid] += rs[tid + off]; rss[tid] += rss[tid + off]; }
        __syncthreads();
    }
    if (tid == 0) {
        float mean = rs[0] / (float)TOT;
        float var  = rss[0] / (float)TOT - mean * mean;
        stat[blockIdx.x * 2 + 0] = mean;
        stat[blockIdx.x * 2 + 1] = rsqrtf(var + 1e-5f);
    }
}

// ---------------- GroupNorm apply + transpose -> fp16 ht ----------------
__global__ void gn_apply(const float* __restrict__ x,
                         const float* __restrict__ w,
                         const float* __restrict__ bb,
                         const float* __restrict__ stat,
                         __half* __restrict__ ht)
{
    __shared__ float t[32][33];
    const int b  = blockIdx.z;
    const int c0 = blockIdx.x * 32;
    const int n0 = blockIdx.y * 32;
    const int tx = threadIdx.x, ty = threadIdx.y;
    const float* xb = x  + (long)b * NC * NSP;
    __half*      hb = ht + (long)b * NSP * NC;

#pragma unroll
    for (int j = 0; j < 4; j++) {
        const int c = c0 + ty + j * 8;
        const int g = c >> 3;
        const float mean = stat[(b * NGRP + g) * 2 + 0];
        const float inv  = stat[(b * NGRP + g) * 2 + 1];
        const float wc = w[c] * inv;
        const float bc = bb[c] - mean * wc;
        t[ty + j * 8][tx] = xb[(long)c * NSP + n0 + tx] * wc + bc;
    }
    __syncthreads();
#pragma unroll
    for (int j = 0; j < 4; j++) {
        const int n = n0 + ty + j * 8;
        hb[(long)n * NC + c0 + tx] = __float2half_rn(t[tx][ty + j * 8]);
    }
}

// =============== fp16 GEMM, cp.async 4-stage pipeline ===============
#define TSZH 5120
#define SMEMB (2 * STAGES * TSZH * 2)   // 81920 bytes

#define GEMM_PREAMBLE \
    extern __shared__ __half smh[]; \
    const uint32_t sb = smem_u32(smh); \
    const int tid = threadIdx.x; \
    const int wid = tid >> 5, lane = tid & 31; \
    const int wm = wid >> 2, wn = wid & 3; \
    const int g = lane >> 2, t = lane & 3; \
    const int bz = blockIdx.z; \
    long bm = (long)blockIdx.y * 128; \
    long bn = (long)blockIdx.x * 128; \
    const int rr2 = tid >> 2, ii2 = tid & 3; \
    float c[4][4][4]; \
    _Pragma("unroll") for (int mi = 0; mi < 4; mi++) \
    _Pragma("unroll") for (int ni = 0; ni < 4; ni++) \
    _Pragma("unroll") for (int j = 0; j < 4; j++) c[mi][ni][j] = 0.f;

#define CPA_ISSUE(buf, k0) do { \
    uint32_t da_ = sb + (uint32_t)(((buf) * TSZH + rr2 * 40 + ii2 * 8) * 2); \
    asm volatile("cp.async.cg.shared.global [%0], [%1], 16;" \
                 :: "r"(da_), "l"(gAh + (long)(k0)) : "memory"); \
    asm volatile("cp.async.cg.shared.global [%0], [%1], 16;" \
                 :: "r"(da_ + 64 * 40 * 2), "l"(gAh + (long)(k0) + 64L * lda) : "memory"); \
    uint32_t db_ = sb + (uint32_t)(((STAGES + (buf)) * TSZH + rr2 * 40 + ii2 * 8) * 2); \
    asm volatile("cp.async.cg.shared.global [%0], [%1], 16;" \
                 :: "r"(db_), "l"(gBh + (long)(k0)) : "memory"); \
    asm volatile("cp.async.cg.shared.global [%0], [%1], 16;" \
                 :: "r"(db_ + 64 * 40 * 2), "l"(gBh + (long)(k0) + 64L * ldb) : "memory"); \
} while (0)

#define CPA_COMMIT() asm volatile("cp.async.commit_group;" ::: "memory")
#define CPA_WAIT()   asm volatile("cp.async.wait_group %0;" :: "n"(STAGES - 2) : "memory")

#define LOAD_FRAGS(buf) \
    uint32_t a[4][4], b[4][2]; \
    { const __half* As = smh + (buf) * TSZH + (wm * 64 + g) * 40 + 2 * t + kk; \
      const __half* Bs = smh + (STAGES + (buf)) * TSZH + (wn * 32 + g) * 40 + 2 * t + kk; \
      _Pragma("unroll") for (int mi = 0; mi < 4; mi++) { \
          const __half* ap = As + mi * 16 * 40; \
          a[mi][0] = *reinterpret_cast<const uint32_t*>(ap); \
          a[mi][1] = *reinterpret_cast<const uint32_t*>(ap + 8 * 40); \
          a[mi][2] = *reinterpret_cast<const uint32_t*>(ap + 8); \
          a[mi][3] = *reinterpret_cast<const uint32_t*>(ap + 8 * 40 + 8); } \
      _Pragma("unroll") for (int ni = 0; ni < 4; ni++) { \
          const __half* bp = Bs + ni * 8 * 40; \
          b[ni][0] = *reinterpret_cast<const uint32_t*>(bp); \
          b[ni][1] = *reinterpret_cast<const uint32_t*>(bp + 8); } }

#define MMA_BODY16(buf) do { \
    _Pragma("unroll") for (int kk = 0; kk < 32; kk += 16) { \
        LOAD_FRAGS(buf) \
        _Pragma("unroll") for (int mi = 0; mi < 4; mi++) \
        _Pragma("unroll") for (int ni = 0; ni < 4; ni++) \
            mma16(c[mi][ni], a[mi], b[ni]); \
    } \
} while (0)

#define MMA_BODY16S(buf) do { \
    _Pragma("unroll") for (int kk = 0; kk < 32; kk += 16) { \
        LOAD_FRAGS(buf) \
        _Pragma("unroll") for (int mi = 0; mi < 4; mi++) { \
            a[mi][0] = hmul2u(a[mi][0], F0[mi]); \
            a[mi][2] = hmul2u(a[mi][2], F0[mi]); \
            a[mi][1] = hmul2u(a[mi][1], F1[mi]); \
            a[mi][3] = hmul2u(a[mi][3], F1[mi]); } \
        _Pragma("unroll") for (int mi = 0; mi < 4; mi++) \
        _Pragma("unroll") for (int ni = 0; ni < 4; ni++) \
            mma16(c[mi][ni], a[mi], b[ni]); \
    } \
} while (0)

#define PIPE_LOOP(NITER, BODY) do { \
    int kload = 0; \
    _Pragma("unroll") for (int s = 0; s < STAGES - 1; s++) { \
        if (s < (NITER)) CPA_ISSUE(s, kload); \
        CPA_COMMIT(); kload += 32; } \
    for (int it = 0; it < (NITER); ++it) { \
        CPA_WAIT(); \
        __syncthreads(); \
        if (it + STAGES - 1 < (NITER)) CPA_ISSUE((it + STAGES - 1) % STAGES, kload); \
        CPA_COMMIT(); kload += 32; \
        BODY; \
    } \
} while (0)

// ---------------------------------------------------------------------------
// merged QKV projection. grid (2, 32, NB*3); kind = z%3 (0=q,1=k,2=v), b=z/3.
// q,k: out[n][o] (ldc=NC), col bias; v: out[o][m] (ldc=NSP), row bias.
// ---------------------------------------------------------------------------
__global__ __launch_bounds__(256, 2)
void qkv_gemm(const __half* __restrict__ ht,
              const __half* __restrict__ wh,
              const float* __restrict__ bq, __half* __restrict__ qt,
              const float* __restrict__ bk, __half* __restrict__ kt,
              const float* __restrict__ bv, __half* __restrict__ vv)
{
    GEMM_PREAMBLE
    const int b = bz / 3, kind = bz % 3;
    const long sCN = (long)NC * NSP;
    const int lda = NC, ldb = NC;

    const __half* gAh;
    const __half* gBh;
    const float* bias;
    __half* oo;
    int ldc, biascol;
    float alpha = 1.f;

    if (kind < 2) {
        // bm over NSP (y), bn over NC (x)
        gAh = ht + (long)b * sCN + (bm + rr2) * (long)NC + ii2 * 8;
        gBh = wh + (long)kind * NC * NC + (bn + rr2) * (long)NC + ii2 * 8;
        bias = kind ? bk : bq;
        oo = (kind ? kt : qt) + (long)b * sCN;
        ldc = NC; biascol = 1;
        if (kind == 0) alpha = 0.0625f;
    } else {
        // v: bm over NC (use x), bn over NSP (use y)
        bm = (long)blockIdx.x * 128;
        bn = (long)blockIdx.y * 128;
        gAh = wh + 2L * NC * NC + (bm + rr2) * (long)NC + ii2 * 8;
        gBh = ht + (long)b * sCN + (bn + rr2) * (long)NC + ii2 * 8;
        bias = bv;
        oo = vv + (long)b * sCN;
        ldc = NSP; biascol = 0;
    }

    PIPE_LOOP(NC >> 5, MMA_BODY16(it % STAGES));

#pragma unroll
    for (int mi = 0; mi < 4; mi++) {
        const long row0 = bm + wm * 64 + mi * 16 + g;
        const long row1 = row0 + 8;
        const float br0 = biascol ? 0.f : bias[row0];
        const float br1 = biascol ? 0.f : bias[row1];
#pragma unroll
        for (int ni = 0; ni < 4; ni++) {
            const long col = bn + wn * 32 + ni * 8 + 2 * t;
            float bc0 = br0, bc1 = br0, bc2 = br1, bc3 = br1;
            if (biascol) { bc0 = bias[col]; bc1 = bias[col + 1]; bc2 = bc0; bc3 = bc1; }
            *reinterpret_cast<__half2*>(oo + row0 * ldc + col) =
                __floats2half2_rn((c[mi][ni][0] + bc0) * alpha, (c[mi][ni][1] + bc1) * alpha);
            *reinterpret_cast<__half2*>(oo + row1 * ldc + col) =
                __floats2half2_rn((c[mi][ni][2] + bc2) * alpha, (c[mi][ni][3] + bc3) * alpha);
        }
    }
}

// ---------------------------------------------------------------------------
// out-projection (fp32 out + residual)
// ---------------------------------------------------------------------------
__global__ __launch_bounds__(256, 2)
void oproj_gemm(const __half* __restrict__ A, int lda,
                const __half* __restrict__ B, long sB, int ldb,
                float* __restrict__ C, long sC, int ldc,
                const float* __restrict__ bias,
                const float* __restrict__ resid, long sR)
{
    GEMM_PREAMBLE
    const __half* gAh = A + (bm + rr2) * (long)lda + ii2 * 8;
    const __half* gBh = B + (long)bz * sB + (bn + rr2) * (long)ldb + ii2 * 8;

    PIPE_LOOP(NC >> 5, MMA_BODY16(it % STAGES));

#pragma unroll
    for (int mi = 0; mi < 4; mi++) {
        const long row0 = bm + wm * 64 + mi * 16 + g;
        const long row1 = row0 + 8;
        const float br0 = bias[row0], br1 = bias[row1];
#pragma unroll
        for (int ni = 0; ni < 4; ni++) {
            const long col = bn + wn * 32 + ni * 8 + 2 * t;
            float2 v0 = make_float2(c[mi][ni][0] + br0, c[mi][ni][1] + br0);
            float2 v1 = make_float2(c[mi][ni][2] + br1, c[mi][ni][3] + br1);
            const float* Rz = resid + (long)bz * sR;
            float2 r0 = *reinterpret_cast<const float2*>(Rz + row0 * ldc + col);
            float2 r1 = *reinterpret_cast<const float2*>(Rz + row1 * ldc + col);
            v0.x += r0.x; v0.y += r0.y; v1.x += r1.x; v1.y += r1.y;
            float* Cz = C + (long)bz * sC;
            *reinterpret_cast<float2*>(Cz + row0 * ldc + col) = v0;
            *reinterpret_cast<float2*>(Cz + row1 * ldc + col) = v1;
        }
    }
}

// ---------------------------------------------------------------------------
// logits GEMM: exp(l - m_tile) as half + (m,s) stats
// ---------------------------------------------------------------------------
__global__ __launch_bounds__(256, 2)
void logits_gemm(const __half* __restrict__ A, long sA, int lda,
                 const __half* __restrict__ B, long sB, int ldb,
                 __half* __restrict__ C, long sC, int ldc,
                 float* __restrict__ pm, float* __restrict__ ps)
{
    GEMM_PREAMBLE
    const __half* gAh = A + (long)bz * sA + (bm + rr2) * (long)lda + ii2 * 8;
    const __half* gBh = B + (long)bz * sB + (bn + rr2) * (long)ldb + ii2 * 8;

    PIPE_LOOP(NC >> 5, MMA_BODY16(it % STAGES));
    __syncthreads();

    float* smf = reinterpret_cast<float*>(smh);
    float* smm = smf;
    float* sms = smf + 512;

#pragma unroll
    for (int mi = 0; mi < 4; mi++)
#pragma unroll
        for (int h = 0; h < 2; h++) {
            float m0 = -1e30f;
#pragma unroll
            for (int ni = 0; ni < 4; ni++)
                m0 = fmaxf(m0, fmaxf(c[mi][ni][2 * h], c[mi][ni][2 * h + 1]));
            m0 = fmaxf(m0, __shfl_xor_sync(0xffffffff, m0, 1));
            m0 = fmaxf(m0, __shfl_xor_sync(0xffffffff, m0, 2));
            if (t == 0) smm[(wm * 64 + mi * 16 + g + 8 * h) * 4 + wn] = m0;
        }
    __syncthreads();

    float mt[4][2];
#pragma unroll
    for (int mi = 0; mi < 4; mi++)
#pragma unroll
        for (int h = 0; h < 2; h++) {
            const int R = wm * 64 + mi * 16 + g + 8 * h;
            float m0 = fmaxf(fmaxf(smm[R * 4 + 0], smm[R * 4 + 1]),
                             fmaxf(smm[R * 4 + 2], smm[R * 4 + 3]));
            mt[mi][h] = m0;
            float s0 = 0.f;
#pragma unroll
            for (int ni = 0; ni < 4; ni++) {
                float e0 = __expf(c[mi][ni][2 * h]     - m0);
                float e1 = __expf(c[mi][ni][2 * h + 1] - m0);
                c[mi][ni][2 * h]     = e0;
                c[mi][ni][2 * h + 1] = e1;
                s0 += e0 + e1;
            }
            s0 += __shfl_xor_sync(0xffffffff, s0, 1);
            s0 += __shfl_xor_sync(0xffffffff, s0, 2);
            if (t == 0) sms[R * 4 + wn] = s0;
        }
    __syncthreads();

    if (wn == 0 && t == 0) {
#pragma unroll
        for (int mi = 0; mi < 4; mi++)
#pragma unroll
            for (int h = 0; h < 2; h++) {
                const int R = wm * 64 + mi * 16 + g + 8 * h;
                const float s0 = sms[R * 4 + 0] + sms[R * 4 + 1]
                               + sms[R * 4 + 2] + sms[R * 4 + 3];
                const long idx = ((long)bz * NSP + bm + R) * NTIL + blockIdx.x;
                pm[idx] = mt[mi][h];
                ps[idx] = s0;
            }
    }

    __half* Cz = C + (long)bz * sC;
#pragma unroll
    for (int mi = 0; mi < 4; mi++) {
        const long row0 = bm + wm * 64 + mi * 16 + g;
        const long row1 = row0 + 8;
#pragma unroll
        for (int ni = 0; ni < 4; ni++) {
            const long col = bn + wn * 32 + ni * 8 + 2 * t;
            *reinterpret_cast<__half2*>(Cz + row0 * ldc + col) =
                __floats2half2_rn(c[mi][ni][0], c[mi][ni][1]);
            *reinterpret_cast<__half2*>(Cz + row1 * ldc + col) =
                __floats2half2_rn(c[mi][ni][2], c[mi][ni][3]);
        }
    }
}

// ---------------------------------------------------------------------------
// combine
// ---------------------------------------------------------------------------
__global__ void combine_kernel(const float* __restrict__ pm,
                               const float* __restrict__ ps,
                               float* __restrict__ sce,
                               float* __restrict__ sci)
{
    const long row = (long)blockIdx.x * 8 + (threadIdx.x >> 5);
    const int lane = threadIdx.x & 31;
    const float m_t = pm[row * NTIL + lane];
    const float s_t = ps[row * NTIL + lane];
    float m = m_t;
#pragma unroll
    for (int off = 16; off > 0; off >>= 1)
        m = fmaxf(m, __shfl_xor_sync(0xffffffff, m, off));
    const float e = __expf(m_t - m);
    float s = s_t * e;
#pragma unroll
    for (int off = 16; off > 0; off >>= 1)
        s += __shfl_xor_sync(0xffffffff, s, off);
    sce[row * NTIL + lane] = e;
    if (lane == 0) sci[row] = 1.f / s;
}

// ---------------------------------------------------------------------------
// PV GEMM split-K (KSPLIT=2) with fragment-level e_t scaling
// ---------------------------------------------------------------------------
__global__ __launch_bounds__(256, 2)
void pv_gemm(const __half* __restrict__ A, long sA, int lda,
             const __half* __restrict__ B, long sB, int ldb,
             float* __restrict__ Cp,
             const float* __restrict__ sce)
{
    GEMM_PREAMBLE
    const int b = bz >> 1, slice = bz & 1;
    const int ko = slice * (NSP / KSPLIT);
    const __half* gAh = A + (long)b * sA + (bm + rr2) * (long)lda + ii2 * 8 + ko;
    const __half* gBh = B + (long)b * sB + (bn + rr2) * (long)ldb + ii2 * 8 + ko;
    const float* scb = sce + ((long)b * NSP + bm) * NTIL;
    const int tbase = ko >> 7;

    uint32_t F0[4], F1[4];

    PIPE_LOOP((NSP / KSPLIT) >> 5,
        if ((it & 3) == 0) {
            const int tm = tbase + (it >> 2);
#pragma unroll
            for (int mi = 0; mi < 4; mi++) {
                const int r0 = wm * 64 + mi * 16 + g;
                F0[mi] = h2u(__float2half2_rn(scb[r0 * NTIL + tm]));
                F1[mi] = h2u(__float2half2_rn(scb[(r0 + 8) * NTIL + tm]));
            }
        }
        MMA_BODY16S(it % STAGES)
    );

    float* Cz = Cp + (long)bz * ((long)NSP * NC);
#pragma unroll
    for (int mi = 0; mi < 4; mi++) {
        const long row0 = bm + wm * 64 + mi * 16 + g;
        const long row1 = row0 + 8;
#pragma unroll
        for (int ni = 0; ni < 4; ni++) {
            const long col = bn + wn * 32 + ni * 8 + 2 * t;
            *reinterpret_cast<float2*>(Cz + row0 * NC + col) =
                make_float2(c[mi][ni][0], c[mi][ni][1]);
            *reinterpret_cast<float2*>(Cz + row1 * NC + col) =
                make_float2(c[mi][ni][2], c[mi][ni][3]);
        }
    }
}

// ---------------------------------------------------------------------------
// reduce split-K partials (2), apply 1/s, convert to fp16 ot
// ---------------------------------------------------------------------------
__global__ void pv_reduce(const float* __restrict__ Cp,
                          const float* __restrict__ sci,
                          __half* __restrict__ ot)
{
    const int b = blockIdx.y;
    const long S = (long)NSP * NC;
    const long i = ((long)blockIdx.x * 256 + threadIdx.x) * 4;
    const float* base = Cp + (long)b * KSPLIT * S + i;

    float4 a0 = *reinterpret_cast<const float4*>(base);
    float4 a1 = *reinterpret_cast<const float4*>(base + S);
    const float iv = sci[(long)b * NSP + (i >> 8)];

    float4 r;
    r.x = (a0.x + a1.x) * iv;
    r.y = (a0.y + a1.y) * iv;
    r.z = (a0.z + a1.z) * iv;
    r.w = (a0.w + a1.w) * iv;

    __half2* o = reinterpret_cast<__half2*>(ot + (long)b * S + i);
    o[0] = __floats2half2_rn(r.x, r.y);
    o[1] = __floats2half2_rn(r.z, r.w);
}

// ---------------------------------------------------------------------------
extern "C" void kernel_launch(void* const* d_in, const int* in_sizes, int n_in,
                              void* d_out, int out_size)
{
    const float* x   = (const float*)d_in[0];
    const float* gnw = (const float*)d_in[1];
    const float* gnb = (const float*)d_in[2];
    const float* wq  = (const float*)d_in[3];
    const float* bq  = (const float*)d_in[4];
    const float* wk  = (const float*)d_in[5];
    const float* bk  = (const float*)d_in[6];
    const float* wv  = (const float*)d_in[7];
    const float* bv  = (const float*)d_in[8];
    const float* wp  = (const float*)d_in[9];
    const float* bp  = (const float*)d_in[10];
    float* out = (float*)d_out;

    __half *ht, *qt, *kt, *v, *ot, *attn, *wh;
    float *otp, *stat, *pm, *ps, *sce, *sci;
    cudaGetSymbolAddress((void**)&ht,   g_ht);
    cudaGetSymbolAddress((void**)&qt,   g_qt);
    cudaGetSymbolAddress((void**)&kt,   g_kt);
    cudaGetSymbolAddress((void**)&v,    g_v);
    cudaGetSymbolAddress((void**)&ot,   g_ot);
    cudaGetSymbolAddress((void**)&attn, g_attn);
    cudaGetSymbolAddress((void**)&wh,   g_wh);
    cudaGetSymbolAddress((void**)&otp,  g_otp);
    cudaGetSymbolAddress((void**)&stat, g_stat);
    cudaGetSymbolAddress((void**)&pm,   g_pm);
    cudaGetSymbolAddress((void**)&ps,   g_ps);
    cudaGetSymbolAddress((void**)&sce,  g_sce);
    cudaGetSymbolAddress((void**)&sci,  g_sci);

    const long sCN = (long)NC * NSP;
    const long sNN = (long)NSP * NSP;

    cudaFuncSetAttribute(qkv_gemm,    cudaFuncAttributeMaxDynamicSharedMemorySize, SMEMB);
    cudaFuncSetAttribute(oproj_gemm,  cudaFuncAttributeMaxDynamicSharedMemorySize, SMEMB);
    cudaFuncSetAttribute(logits_gemm, cudaFuncAttributeMaxDynamicSharedMemorySize, SMEMB);
    cudaFuncSetAttribute(pv_gemm,     cudaFuncAttributeMaxDynamicSharedMemorySize, SMEMB);

    // 0) weights -> fp16
    wconv<<<dim3(NC * NC / 1024, 4), 256>>>(wq, wk, wv, wp, wh);

    // 1) GroupNorm
    gn_stats<<<NB * NGRP, 256>>>(x, stat);
    gn_apply<<<dim3(NC / 32, NSP / 32, NB), dim3(32, 8)>>>(x, gnw, gnb, stat, ht);

    // 2) QKV merged (384 CTAs)
    dim3 gQKV(NC / 128, NSP / 128, NB * 3);
    qkv_gemm<<<gQKV, 256, SMEMB>>>(ht, wh, bq, qt, bk, kt, bv, v);

    // 3) logits with fused exp + tile stats
    dim3 gS(NSP / 128, NSP / 128, NB);
    logits_gemm<<<gS, 256, SMEMB>>>(qt, sCN, NC, kt, sCN, NC, attn, sNN, NSP,
                                    pm, ps);

    // 4) combine
    combine_kernel<<<NB * NSP / 8, 256>>>(pm, ps, sce, sci);

    // 5) PV split-K (256 CTAs) + reduce
    dim3 gO(NC / 128, NSP / 128, NB * KSPLIT);
    pv_gemm<<<gO, 256, SMEMB>>>(attn, sNN, NSP, v, sCN, NSP, otp, sce);
    pv_reduce<<<dim3((unsigned)(sCN / 1024), NB), 256>>>(otp, sci, ot);

    // 6) out-projection + residual
    dim3 gP(NSP / 128, NC / 128, NB);
    oproj_gemm<<<gP, 256, SMEMB>>>(wh + 3L * NC * NC, NC, ot, sCN, NC,
                                   out, sCN, NSP, bp, x, sCN);
}

// round 13
// speedup vs baseline: 2.3367x; 1.1593x over previous
#include <cuda_runtime.h>
#include <cuda_fp16.h>
#include <cstdint>

#define NB   2
#define NC   256
#define NSP  4096
#define NGRP 32
#define CPG  8
#define NTIL 32
#define KSPLIT 2
#define STAGES 3
#define BK    64
#define STRD  72                 // halves per tile row (64 + 8 pad)
#define ATS   (128 * STRD)       // halves per tile stage

// ---------------- scratch (no allocation allowed) ----------------
__device__ __half g_ht  [(size_t)NB * NC * NSP];
__device__ __half g_qt  [(size_t)NB * NC * NSP];
__device__ __half g_kt  [(size_t)NB * NC * NSP];
__device__ __half g_v   [(size_t)NB * NC * NSP];
__device__ __half g_ot  [(size_t)NB * NC * NSP];
__device__ __half g_attn[(size_t)NB * NSP * NSP];
__device__ float  g_otp [(size_t)NB * KSPLIT * NC * NSP];
__device__ __half g_wh  [4 * NC * NC];
__device__ float  g_stat[NB * NGRP * 2];
__device__ float  g_pm  [(size_t)NB * NSP * NTIL];
__device__ float  g_ps  [(size_t)NB * NSP * NTIL];
__device__ float  g_sce [(size_t)NB * NSP * NTIL];
__device__ float  g_sci [(size_t)NB * NSP];

// ---------------- helpers ----------------
__device__ __forceinline__ uint32_t smem_u32(const void* p) {
    uint32_t r;
    asm("{ .reg .u64 t; cvta.to.shared.u64 t, %1; cvt.u32.u64 %0, t; }"
        : "=r"(r) : "l"(p));
    return r;
}
__device__ __forceinline__ void mma16(float* c, const uint32_t* a, const uint32_t* b) {
    asm volatile(
        "mma.sync.aligned.m16n8k16.row.col.f32.f16.f16.f32 "
        "{%0,%1,%2,%3}, {%4,%5,%6,%7}, {%8,%9}, {%0,%1,%2,%3};\n"
        : "+f"(c[0]), "+f"(c[1]), "+f"(c[2]), "+f"(c[3])
        : "r"(a[0]), "r"(a[1]), "r"(a[2]), "r"(a[3]),
          "r"(b[0]), "r"(b[1]));
}
__device__ __forceinline__ void ldsm4(uint32_t* r, uint32_t addr) {
    asm volatile(
        "ldmatrix.sync.aligned.m8n8.x4.shared.b16 {%0,%1,%2,%3}, [%4];"
        : "=r"(r[0]), "=r"(r[1]), "=r"(r[2]), "=r"(r[3]) : "r"(addr));
}
__device__ __forceinline__ uint32_t hmul2u(uint32_t a, uint32_t f) {
    __half2 r = __hmul2(*reinterpret_cast<__half2*>(&a),
                        *reinterpret_cast<__half2*>(&f));
    return *reinterpret_cast<uint32_t*>(&r);
}
__device__ __forceinline__ uint32_t h2u(__half2 h) {
    return *reinterpret_cast<uint32_t*>(&h);
}

// ---------------- weight fp32 -> fp16 ----------------
__global__ void wconv(const float* __restrict__ wq, const float* __restrict__ wk,
                      const float* __restrict__ wv, const float* __restrict__ wp,
                      __half* __restrict__ wh)
{
    const int z = blockIdx.y;
    const float* w = z == 0 ? wq : z == 1 ? wk : z == 2 ? wv : wp;
    const int i = (blockIdx.x * 256 + threadIdx.x) * 4;
    float4 v = *reinterpret_cast<const float4*>(w + i);
    __half2* o = reinterpret_cast<__half2*>(wh + z * NC * NC + i);
    o[0] = __floats2half2_rn(v.x, v.y);
    o[1] = __floats2half2_rn(v.z, v.w);
}

// ---------------- GroupNorm stats ----------------
__global__ void gn_stats(const float* __restrict__ x, float* __restrict__ stat)
{
    const int b = blockIdx.x >> 5;
    const int g = blockIdx.x & 31;
    const float* xp = x + ((long)b * NC + (long)g * CPG) * NSP;
    const int tid = threadIdx.x;
    const int TOT = CPG * NSP;

    float s = 0.f, ss = 0.f;
    for (int i = tid * 4; i < TOT; i += 1024) {
        float4 v = *reinterpret_cast<const float4*>(xp + i);
        s  += v.x + v.y + v.z + v.w;
        ss += v.x * v.x + v.y * v.y + v.z * v.z + v.w * v.w;
    }
    __shared__ float rs[256], rss[256];
    rs[tid] = s; rss[tid] = ss;
    __syncthreads();
    for (int off = 128; off > 0; off >>= 1) {
        if (tid < off) { rs[tid] += rs[tid + off]; rss[tid] += rss[tid + off]; }
        __syncthreads();
    }
    if (tid == 0) {
        float mean = rs[0] / (float)TOT;
        float var  = rss[0] / (float)TOT - mean * mean;
        stat[blockIdx.x * 2 + 0] = mean;
        stat[blockIdx.x * 2 + 1] = rsqrtf(var + 1e-5f);
    }
}

// ---------------- GroupNorm apply + transpose -> fp16 ht ----------------
__global__ void gn_apply(const float* __restrict__ x,
                         const float* __restrict__ w,
                         const float* __restrict__ bb,
                         const float* __restrict__ stat,
                         __half* __restrict__ ht)
{
    __shared__ float t[32][33];
    const int b  = blockIdx.z;
    const int c0 = blockIdx.x * 32;
    const int n0 = blockIdx.y * 32;
    const int tx = threadIdx.x, ty = threadIdx.y;
    const float* xb = x  + (long)b * NC * NSP;
    __half*      hb = ht + (long)b * NSP * NC;

#pragma unroll
    for (int j = 0; j < 4; j++) {
        const int c = c0 + ty + j * 8;
        const int g = c >> 3;
        const float mean = stat[(b * NGRP + g) * 2 + 0];
        const float inv  = stat[(b * NGRP + g) * 2 + 1];
        const float wc = w[c] * inv;
        const float bc = bb[c] - mean * wc;
        t[ty + j * 8][tx] = xb[(long)c * NSP + n0 + tx] * wc + bc;
    }
    __syncthreads();
#pragma unroll
    for (int j = 0; j < 4; j++) {
        const int n = n0 + ty + j * 8;
        hb[(long)n * NC + c0 + tx] = __float2half_rn(t[tx][ty + j * 8]);
    }
}

// =============== fp16 GEMM, cp.async 3-stage / BK=64 / ldmatrix ===============
#define SMEMB (2 * STAGES * ATS * 2)   // 110592 bytes

#define GEMM_PREAMBLE \
    extern __shared__ __half smh[]; \
    const uint32_t sb = smem_u32(smh); \
    const int tid = threadIdx.x; \
    const int wid = tid >> 5, lane = tid & 31; \
    const int wm = wid >> 2, wn = wid & 3; \
    const int g = lane >> 2, t = lane & 3; \
    const int jlo = (lane >> 3) & 1, jhi = lane >> 4, r8 = lane & 7; \
    const int bz = blockIdx.z; \
    long bm = (long)blockIdx.y * 128; \
    long bn = (long)blockIdx.x * 128; \
    const int rr = tid >> 3, ii = tid & 7; \
    float c[4][4][4]; \
    _Pragma("unroll") for (int mi = 0; mi < 4; mi++) \
    _Pragma("unroll") for (int ni = 0; ni < 4; ni++) \
    _Pragma("unroll") for (int j = 0; j < 4; j++) c[mi][ni][j] = 0.f;

#define CPA_ISSUE(buf, k0) do { \
    _Pragma("unroll") for (int r_ = 0; r_ < 4; r_++) { \
        uint32_t da_ = sb + (uint32_t)(((buf) * ATS + (rr + 32 * r_) * STRD + ii * 8) * 2); \
        asm volatile("cp.async.cg.shared.global [%0], [%1], 16;" \
                     :: "r"(da_), "l"(gAh + (long)(k0) + 32L * r_ * lda) : "memory"); } \
    _Pragma("unroll") for (int r_ = 0; r_ < 4; r_++) { \
        uint32_t db_ = sb + (uint32_t)(((STAGES + (buf)) * ATS + (rr + 32 * r_) * STRD + ii * 8) * 2); \
        asm volatile("cp.async.cg.shared.global [%0], [%1], 16;" \
                     :: "r"(db_), "l"(gBh + (long)(k0) + 32L * r_ * ldb) : "memory"); } \
} while (0)

#define CPA_COMMIT() asm volatile("cp.async.commit_group;" ::: "memory")
#define CPA_WAIT()   asm volatile("cp.async.wait_group %0;" :: "n"(STAGES - 2) : "memory")

#define LOAD_FRAGS(buf, kk) \
    uint32_t a[4][4], b[4][2]; \
    { const uint32_t aAddr = sb + (uint32_t)((((buf) * ATS) \
            + (wm * 64 + jlo * 8 + r8) * STRD + jhi * 8 + (kk)) * 2); \
      const uint32_t bAddr = sb + (uint32_t)((((STAGES + (buf)) * ATS) \
            + (wn * 32 + jhi * 8 + r8) * STRD + jlo * 8 + (kk)) * 2); \
      _Pragma("unroll") for (int mi = 0; mi < 4; mi++) \
          ldsm4(a[mi], aAddr + (uint32_t)(mi * 16 * STRD * 2)); \
      _Pragma("unroll") for (int nip = 0; nip < 2; nip++) { \
          uint32_t bt[4]; \
          ldsm4(bt, bAddr + (uint32_t)(nip * 16 * STRD * 2)); \
          b[2 * nip][0] = bt[0]; b[2 * nip][1] = bt[1]; \
          b[2 * nip + 1][0] = bt[2]; b[2 * nip + 1][1] = bt[3]; } }

#define MMA_BODY16(buf) do { \
    _Pragma("unroll") for (int kk = 0; kk < BK; kk += 16) { \
        LOAD_FRAGS(buf, kk) \
        _Pragma("unroll") for (int mi = 0; mi < 4; mi++) \
        _Pragma("unroll") for (int ni = 0; ni < 4; ni++) \
            mma16(c[mi][ni], a[mi], b[ni]); \
    } \
} while (0)

#define MMA_BODY16S(buf) do { \
    _Pragma("unroll") for (int kk = 0; kk < BK; kk += 16) { \
        LOAD_FRAGS(buf, kk) \
        _Pragma("unroll") for (int mi = 0; mi < 4; mi++) { \
            a[mi][0] = hmul2u(a[mi][0], F0[mi]); \
            a[mi][2] = hmul2u(a[mi][2], F0[mi]); \
            a[mi][1] = hmul2u(a[mi][1], F1[mi]); \
            a[mi][3] = hmul2u(a[mi][3], F1[mi]); } \
        _Pragma("unroll") for (int mi = 0; mi < 4; mi++) \
        _Pragma("unroll") for (int ni = 0; ni < 4; ni++) \
            mma16(c[mi][ni], a[mi], b[ni]); \
    } \
} while (0)

#define PIPE_LOOP(NITER, BODY) do { \
    int kload = 0; \
    _Pragma("unroll") for (int s = 0; s < STAGES - 1; s++) { \
        if (s < (NITER)) CPA_ISSUE(s, kload); \
        CPA_COMMIT(); kload += BK; } \
    for (int it = 0; it < (NITER); ++it) { \
        CPA_WAIT(); \
        __syncthreads(); \
        if (it + STAGES - 1 < (NITER)) CPA_ISSUE((it + STAGES - 1) % STAGES, kload); \
        CPA_COMMIT(); kload += BK; \
        BODY; \
    } \
} while (0)

// ---------------------------------------------------------------------------
// merged QKV projection. grid (2, 32, NB*3); kind = z%3 (0=q,1=k,2=v)
// ---------------------------------------------------------------------------
__global__ __launch_bounds__(256, 2)
void qkv_gemm(const __half* __restrict__ ht,
              const __half* __restrict__ wh,
              const float* __restrict__ bq, __half* __restrict__ qt,
              const float* __restrict__ bk, __half* __restrict__ kt,
              const float* __restrict__ bv, __half* __restrict__ vv)
{
    GEMM_PREAMBLE
    const int b = bz / 3, kind = bz % 3;
    const long sCN = (long)NC * NSP;
    const int lda = NC, ldb = NC;

    const __half* gAh;
    const __half* gBh;
    const float* bias;
    __half* oo;
    int ldc, biascol;
    float alpha = 1.f;

    if (kind < 2) {
        gAh = ht + (long)b * sCN + (bm + rr) * (long)NC + ii * 8;
        gBh = wh + (long)kind * NC * NC + (bn + rr) * (long)NC + ii * 8;
        bias = kind ? bk : bq;
        oo = (kind ? kt : qt) + (long)b * sCN;
        ldc = NC; biascol = 1;
        if (kind == 0) alpha = 0.0625f;
    } else {
        bm = (long)blockIdx.x * 128;
        bn = (long)blockIdx.y * 128;
        gAh = wh + 2L * NC * NC + (bm + rr) * (long)NC + ii * 8;
        gBh = ht + (long)b * sCN + (bn + rr) * (long)NC + ii * 8;
        bias = bv;
        oo = vv + (long)b * sCN;
        ldc = NSP; biascol = 0;
    }

    PIPE_LOOP(NC / BK, MMA_BODY16(it % STAGES));

#pragma unroll
    for (int mi = 0; mi < 4; mi++) {
        const long row0 = bm + wm * 64 + mi * 16 + g;
        const long row1 = row0 + 8;
        const float br0 = biascol ? 0.f : bias[row0];
        const float br1 = biascol ? 0.f : bias[row1];
#pragma unroll
        for (int ni = 0; ni < 4; ni++) {
            const long col = bn + wn * 32 + ni * 8 + 2 * t;
            float bc0 = br0, bc1 = br0, bc2 = br1, bc3 = br1;
            if (biascol) { bc0 = bias[col]; bc1 = bias[col + 1]; bc2 = bc0; bc3 = bc1; }
            *reinterpret_cast<__half2*>(oo + row0 * ldc + col) =
                __floats2half2_rn((c[mi][ni][0] + bc0) * alpha, (c[mi][ni][1] + bc1) * alpha);
            *reinterpret_cast<__half2*>(oo + row1 * ldc + col) =
                __floats2half2_rn((c[mi][ni][2] + bc2) * alpha, (c[mi][ni][3] + bc3) * alpha);
        }
    }
}

// ---------------------------------------------------------------------------
// out-projection (fp32 out + residual)
// ---------------------------------------------------------------------------
__global__ __launch_bounds__(256, 2)
void oproj_gemm(const __half* __restrict__ A, int lda,
                const __half* __restrict__ B, long sB, int ldb,
                float* __restrict__ C, long sC, int ldc,
                const float* __restrict__ bias,
                const float* __restrict__ resid, long sR)
{
    GEMM_PREAMBLE
    const __half* gAh = A + (bm + rr) * (long)lda + ii * 8;
    const __half* gBh = B + (long)bz * sB + (bn + rr) * (long)ldb + ii * 8;

    PIPE_LOOP(NC / BK, MMA_BODY16(it % STAGES));

#pragma unroll
    for (int mi = 0; mi < 4; mi++) {
        const long row0 = bm + wm * 64 + mi * 16 + g;
        const long row1 = row0 + 8;
        const float br0 = bias[row0], br1 = bias[row1];
#pragma unroll
        for (int ni = 0; ni < 4; ni++) {
            const long col = bn + wn * 32 + ni * 8 + 2 * t;
            float2 v0 = make_float2(c[mi][ni][0] + br0, c[mi][ni][1] + br0);
            float2 v1 = make_float2(c[mi][ni][2] + br1, c[mi][ni][3] + br1);
            const float* Rz = resid + (long)bz * sR;
            float2 r0 = *reinterpret_cast<const float2*>(Rz + row0 * ldc + col);
            float2 r1 = *reinterpret_cast<const float2*>(Rz + row1 * ldc + col);
            v0.x += r0.x; v0.y += r0.y; v1.x += r1.x; v1.y += r1.y;
            float* Cz = C + (long)bz * sC;
            *reinterpret_cast<float2*>(Cz + row0 * ldc + col) = v0;
            *reinterpret_cast<float2*>(Cz + row1 * ldc + col) = v1;
        }
    }
}

// ---------------------------------------------------------------------------
// logits GEMM: exp(l - m_tile) as half + (m,s) stats
// ---------------------------------------------------------------------------
__global__ __launch_bounds__(256, 2)
void logits_gemm(const __half* __restrict__ A, long sA, int lda,
                 const __half* __restrict__ B, long sB, int ldb,
                 __half* __restrict__ C, long sC, int ldc,
                 float* __restrict__ pm, float* __restrict__ ps)
{
    GEMM_PREAMBLE
    const __half* gAh = A + (long)bz * sA + (bm + rr) * (long)lda + ii * 8;
    const __half* gBh = B + (long)bz * sB + (bn + rr) * (long)ldb + ii * 8;

    PIPE_LOOP(NC / BK, MMA_BODY16(it % STAGES));
    __syncthreads();

    float* smf = reinterpret_cast<float*>(smh);
    float* smm = smf;
    float* sms = smf + 512;

#pragma unroll
    for (int mi = 0; mi < 4; mi++)
#pragma unroll
        for (int h = 0; h < 2; h++) {
            float m0 = -1e30f;
#pragma unroll
            for (int ni = 0; ni < 4; ni++)
                m0 = fmaxf(m0, fmaxf(c[mi][ni][2 * h], c[mi][ni][2 * h + 1]));
            m0 = fmaxf(m0, __shfl_xor_sync(0xffffffff, m0, 1));
            m0 = fmaxf(m0, __shfl_xor_sync(0xffffffff, m0, 2));
            if (t == 0) smm[(wm * 64 + mi * 16 + g + 8 * h) * 4 + wn] = m0;
        }
    __syncthreads();

    float mt[4][2];
#pragma unroll
    for (int mi = 0; mi < 4; mi++)
#pragma unroll
        for (int h = 0; h < 2; h++) {
            const int R = wm * 64 + mi * 16 + g + 8 * h;
            float m0 = fmaxf(fmaxf(smm[R * 4 + 0], smm[R * 4 + 1]),
                             fmaxf(smm[R * 4 + 2], smm[R * 4 + 3]));
            mt[mi][h] = m0;
            float s0 = 0.f;
#pragma unroll
            for (int ni = 0; ni < 4; ni++) {
                float e0 = __expf(c[mi][ni][2 * h]     - m0);
                float e1 = __expf(c[mi][ni][2 * h + 1] - m0);
                c[mi][ni][2 * h]     = e0;
                c[mi][ni][2 * h + 1] = e1;
                s0 += e0 + e1;
            }
            s0 += __shfl_xor_sync(0xffffffff, s0, 1);
            s0 += __shfl_xor_sync(0xffffffff, s0, 2);
            if (t == 0) sms[R * 4 + wn] = s0;
        }
    __syncthreads();

    if (wn == 0 && t == 0) {
#pragma unroll
        for (int mi = 0; mi < 4; mi++)
#pragma unroll
            for (int h = 0; h < 2; h++) {
                const int R = wm * 64 + mi * 16 + g + 8 * h;
                const float s0 = sms[R * 4 + 0] + sms[R * 4 + 1]
                               + sms[R * 4 + 2] + sms[R * 4 + 3];
                const long idx = ((long)bz * NSP + bm + R) * NTIL + blockIdx.x;
                pm[idx] = mt[mi][h];
                ps[idx] = s0;
            }
    }

    __half* Cz = C + (long)bz * sC;
#pragma unroll
    for (int mi = 0; mi < 4; mi++) {
        const long row0 = bm + wm * 64 + mi * 16 + g;
        const long row1 = row0 + 8;
#pragma unroll
        for (int ni = 0; ni < 4; ni++) {
            const long col = bn + wn * 32 + ni * 8 + 2 * t;
            *reinterpret_cast<__half2*>(Cz + row0 * ldc + col) =
                __floats2half2_rn(c[mi][ni][0], c[mi][ni][1]);
            *reinterpret_cast<__half2*>(Cz + row1 * ldc + col) =
                __floats2half2_rn(c[mi][ni][2], c[mi][ni][3]);
        }
    }
}

// ---------------------------------------------------------------------------
// combine
// ---------------------------------------------------------------------------
__global__ void combine_kernel(const float* __restrict__ pm,
                               const float* __restrict__ ps,
                               float* __restrict__ sce,
                               float* __restrict__ sci)
{
    const long row = (long)blockIdx.x * 8 + (threadIdx.x >> 5);
    const int lane = threadIdx.x & 31;
    const float m_t = pm[row * NTIL + lane];
    const float s_t = ps[row * NTIL + lane];
    float m = m_t;
#pragma unroll
    for (int off = 16; off > 0; off >>= 1)
        m = fmaxf(m, __shfl_xor_sync(0xffffffff, m, off));
    const float e = __expf(m_t - m);
    float s = s_t * e;
#pragma unroll
    for (int off = 16; off > 0; off >>= 1)
        s += __shfl_xor_sync(0xffffffff, s, off);
    sce[row * NTIL + lane] = e;
    if (lane == 0) sci[row] = 1.f / s;
}

// ---------------------------------------------------------------------------
// PV GEMM split-K (KSPLIT=2) with fragment-level e_t scaling
// ---------------------------------------------------------------------------
__global__ __launch_bounds__(256, 2)
void pv_gemm(const __half* __restrict__ A, long sA, int lda,
             const __half* __restrict__ B, long sB, int ldb,
             float* __restrict__ Cp,
             const float* __restrict__ sce)
{
    GEMM_PREAMBLE
    const int b = bz >> 1, slice = bz & 1;
    const int ko = slice * (NSP / KSPLIT);
    const __half* gAh = A + (long)b * sA + (bm + rr) * (long)lda + ii * 8 + ko;
    const __half* gBh = B + (long)b * sB + (bn + rr) * (long)ldb + ii * 8 + ko;
    const float* scb = sce + ((long)b * NSP + bm) * NTIL;
    const int tbase = ko >> 7;

    uint32_t F0[4], F1[4];

    PIPE_LOOP((NSP / KSPLIT) / BK,
        if ((it & 1) == 0) {
            const int tm = tbase + (it >> 1);
#pragma unroll
            for (int mi = 0; mi < 4; mi++) {
                const int r0 = wm * 64 + mi * 16 + g;
                F0[mi] = h2u(__float2half2_rn(scb[r0 * NTIL + tm]));
                F1[mi] = h2u(__float2half2_rn(scb[(r0 + 8) * NTIL + tm]));
            }
        }
        MMA_BODY16S(it % STAGES)
    );

    float* Cz = Cp + (long)bz * ((long)NSP * NC);
#pragma unroll
    for (int mi = 0; mi < 4; mi++) {
        const long row0 = bm + wm * 64 + mi * 16 + g;
        const long row1 = row0 + 8;
#pragma unroll
        for (int ni = 0; ni < 4; ni++) {
            const long col = bn + wn * 32 + ni * 8 + 2 * t;
            *reinterpret_cast<float2*>(Cz + row0 * NC + col) =
                make_float2(c[mi][ni][0], c[mi][ni][1]);
            *reinterpret_cast<float2*>(Cz + row1 * NC + col) =
                make_float2(c[mi][ni][2], c[mi][ni][3]);
        }
    }
}

// ---------------------------------------------------------------------------
// reduce split-K partials (2), apply 1/s, convert to fp16 ot
// ---------------------------------------------------------------------------
__global__ void pv_reduce(const float* __restrict__ Cp,
                          const float* __restrict__ sci,
                          __half* __restrict__ ot)
{
    const int b = blockIdx.y;
    const long S = (long)NSP * NC;
    const long i = ((long)blockIdx.x * 256 + threadIdx.x) * 4;
    const float* base = Cp + (long)b * KSPLIT * S + i;

    float4 a0 = *reinterpret_cast<const float4*>(base);
    float4 a1 = *reinterpret_cast<const float4*>(base + S);
    const float iv = sci[(long)b * NSP + (i >> 8)];

    float4 r;
    r.x = (a0.x + a1.x) * iv;
    r.y = (a0.y + a1.y) * iv;
    r.z = (a0.z + a1.z) * iv;
    r.w = (a0.w + a1.w) * iv;

    __half2* o = reinterpret_cast<__half2*>(ot + (long)b * S + i);
    o[0] = __floats2half2_rn(r.x, r.y);
    o[1] = __floats2half2_rn(r.z, r.w);
}

// ---------------------------------------------------------------------------
extern "C" void kernel_launch(void* const* d_in, const int* in_sizes, int n_in,
                              void* d_out, int out_size)
{
    const float* x   = (const float*)d_in[0];
    const float* gnw = (const float*)d_in[1];
    const float* gnb = (const float*)d_in[2];
    const float* wq  = (const float*)d_in[3];
    const float* bq  = (const float*)d_in[4];
    const float* wk  = (const float*)d_in[5];
    const float* bk  = (const float*)d_in[6];
    const float* wv  = (const float*)d_in[7];
    const float* bv  = (const float*)d_in[8];
    const float* wp  = (const float*)d_in[9];
    const float* bp  = (const float*)d_in[10];
    float* out = (float*)d_out;

    __half *ht, *qt, *kt, *v, *ot, *attn, *wh;
    float *otp, *stat, *pm, *ps, *sce, *sci;
    cudaGetSymbolAddress((void**)&ht,   g_ht);
    cudaGetSymbolAddress((void**)&qt,   g_qt);
    cudaGetSymbolAddress((void**)&kt,   g_kt);
    cudaGetSymbolAddress((void**)&v,    g_v);
    cudaGetSymbolAddress((void**)&ot,   g_ot);
    cudaGetSymbolAddress((void**)&attn, g_attn);
    cudaGetSymbolAddress((void**)&wh,   g_wh);
    cudaGetSymbolAddress((void**)&otp,  g_otp);
    cudaGetSymbolAddress((void**)&stat, g_stat);
    cudaGetSymbolAddress((void**)&pm,   g_pm);
    cudaGetSymbolAddress((void**)&ps,   g_ps);
    cudaGetSymbolAddress((void**)&sce,  g_sce);
    cudaGetSymbolAddress((void**)&sci,  g_sci);

    const long sCN = (long)NC * NSP;
    const long sNN = (long)NSP * NSP;

    cudaFuncSetAttribute(qkv_gemm,    cudaFuncAttributeMaxDynamicSharedMemorySize, SMEMB);
    cudaFuncSetAttribute(oproj_gemm,  cudaFuncAttributeMaxDynamicSharedMemorySize, SMEMB);
    cudaFuncSetAttribute(logits_gemm, cudaFuncAttributeMaxDynamicSharedMemorySize, SMEMB);
    cudaFuncSetAttribute(pv_gemm,     cudaFuncAttributeMaxDynamicSharedMemorySize, SMEMB);

    // 0) weights -> fp16
    wconv<<<dim3(NC * NC / 1024, 4), 256>>>(wq, wk, wv, wp, wh);

    // 1) GroupNorm
    gn_stats<<<NB * NGRP, 256>>>(x, stat);
    gn_apply<<<dim3(NC / 32, NSP / 32, NB), dim3(32, 8)>>>(x, gnw, gnb, stat, ht);

    // 2) QKV merged (384 CTAs)
    dim3 gQKV(NC / 128, NSP / 128, NB * 3);
    qkv_gemm<<<gQKV, 256, SMEMB>>>(ht, wh, bq, qt, bk, kt, bv, v);

    // 3) logits with fused exp + tile stats
    dim3 gS(NSP / 128, NSP / 128, NB);
    logits_gemm<<<gS, 256, SMEMB>>>(qt, sCN, NC, kt, sCN, NC, attn, sNN, NSP,
                                    pm, ps);

    // 4) combine
    combine_kernel<<<NB * NSP / 8, 256>>>(pm, ps, sce, sci);

    // 5) PV split-K (256 CTAs) + reduce
    dim3 gO(NC / 128, NSP / 128, NB * KSPLIT);
    pv_gemm<<<gO, 256, SMEMB>>>(attn, sNN, NSP, v, sCN, NSP, otp, sce);
    pv_reduce<<<dim3((unsigned)(sCN / 1024), NB), 256>>>(otp, sci, ot);

    // 6) out-projection + residual
    dim3 gP(NSP / 128, NC / 128, NB);
    oproj_gemm<<<gP, 256, SMEMB>>>(wh + 3L * NC * NC, NC, ot, sCN, NC,
                                   out, sCN, NSP, bp, x, sCN);
}